// round 6
// baseline (speedup 1.0000x reference)
#include <cuda_runtime.h>
#include <cuda_bf16.h>
#include <cstdint>
#include <cstddef>

#define BATCH   4
#define C       64
#define NPIX    4096
#define NGROUPS 32
#define XPAD    132

// ---------------- scratch (device globals; no runtime allocation) ------------
__device__ __nv_bfloat16 g_qh[BATCH * NPIX * C];   // [b][n][c] rows of 128B
__device__ __nv_bfloat16 g_ql[BATCH * NPIX * C];
__device__ __nv_bfloat16 g_kh[BATCH * NPIX * C];
__device__ __nv_bfloat16 g_kl[BATCH * NPIX * C];
__device__ __nv_bfloat16 g_vh[BATCH * NPIX * C];
__device__ __nv_bfloat16 g_vl[BATCH * NPIX * C];
__device__ float         g_stats[BATCH * NGROUPS * 2];

extern __shared__ char dynsm[];

// ---------------- helpers ----------------------------------------------------
__device__ __forceinline__ uint32_t smem_u32(const void* p) {
    uint32_t a;
    asm("{ .reg .u64 t; cvta.to.shared.u64 t, %1; cvt.u32.u64 %0, t; }" : "=r"(a) : "l"(p));
    return a;
}
#define SWZ(o) ((o) ^ (((o) >> 3) & 0x70))

#define CP_ASYNC(dst, src) \
    asm volatile("cp.async.cg.shared.global [%0], [%1], 16;" :: "r"(dst), "l"(src) : "memory")
#define CP_COMMIT asm volatile("cp.async.commit_group;" ::: "memory")
#define CP_WAIT1  asm volatile("cp.async.wait_group 1;" ::: "memory")
#define CP_WAIT0  asm volatile("cp.async.wait_group 0;" ::: "memory")

#define LDSM_X4(r, a) \
    asm volatile("ldmatrix.sync.aligned.m8n8.x4.shared.b16 {%0,%1,%2,%3}, [%4];" \
        : "=r"((r)[0]), "=r"((r)[1]), "=r"((r)[2]), "=r"((r)[3]) : "r"(a))
#define LDSM_X4T(r, a) \
    asm volatile("ldmatrix.sync.aligned.m8n8.x4.trans.shared.b16 {%0,%1,%2,%3}, [%4];" \
        : "=r"((r)[0]), "=r"((r)[1]), "=r"((r)[2]), "=r"((r)[3]) : "r"(a))

// D += A * B  (m16n8k16, bf16 in, f32 accum)
#define MMA(c, a, b0, b1) \
    asm volatile("mma.sync.aligned.m16n8k16.row.col.f32.bf16.bf16.f32 " \
        "{%0,%1,%2,%3}, {%4,%5,%6,%7}, {%8,%9}, {%0,%1,%2,%3};" \
        : "+f"((c)[0]), "+f"((c)[1]), "+f"((c)[2]), "+f"((c)[3]) \
        : "r"((a)[0]), "r"((a)[1]), "r"((a)[2]), "r"((a)[3]), "r"(b0), "r"(b1))

__device__ __forceinline__ uint32_t pack_bf16x2(float lo, float hi) {
    uint32_t r;
    asm("cvt.rn.bf16x2.f32 %0, %1, %2;" : "=r"(r) : "f"(hi), "f"(lo));
    return r;
}

// ============================================================================
// K0: GroupNorm statistics (512 threads for latency hiding)
// ============================================================================
__global__ void __launch_bounds__(512) gn_stats_kernel(const float* __restrict__ x) {
    int g = blockIdx.x, b = blockIdx.y;
    const float* base = x + ((size_t)b * C + (size_t)g * 2) * NPIX;
    float s = 0.f, s2 = 0.f;
    const float4* p4 = (const float4*)base;
    for (int idx = threadIdx.x; idx < (2 * NPIX) / 4; idx += blockDim.x) {
        float4 v = p4[idx];
        s  += v.x + v.y + v.z + v.w;
        s2 += v.x * v.x + v.y * v.y + v.z * v.z + v.w * v.w;
    }
    __shared__ float rs[32], rs2[32];
    #pragma unroll
    for (int o = 16; o; o >>= 1) {
        s  += __shfl_xor_sync(0xffffffffu, s,  o);
        s2 += __shfl_xor_sync(0xffffffffu, s2, o);
    }
    int lane = threadIdx.x & 31, w = threadIdx.x >> 5;
    if (lane == 0) { rs[w] = s; rs2[w] = s2; }
    __syncthreads();
    if (w == 0) {
        s  = (lane < (int)(blockDim.x >> 5)) ? rs[lane]  : 0.f;
        s2 = (lane < (int)(blockDim.x >> 5)) ? rs2[lane] : 0.f;
        #pragma unroll
        for (int o = 16; o; o >>= 1) {
            s  += __shfl_xor_sync(0xffffffffu, s,  o);
            s2 += __shfl_xor_sync(0xffffffffu, s2, o);
        }
        if (lane == 0) {
            const float invn = 1.f / (2.f * NPIX);
            float mean = s * invn;
            float var  = s2 * invn - mean * mean;
            g_stats[(b * NGROUPS + g) * 2 + 0] = mean;
            g_stats[(b * NGROUPS + g) * 2 + 1] = rsqrtf(var + 1e-5f);
        }
    }
}

// ============================================================================
// K1: HMMA QKV projection.  D[i][o] = xn^T[i][c] * W^T[c][o]  (3-term split).
// A = xn^T (attn-Q layout, LDSM_X4), B = W^T (attn-V layout, LDSM_X4T).
// Thread accum pair = adjacent (o,o+1) -> direct packed bf16x2 gmem store.
// Smem: XNH@0 XNL@16K | WT[p] @32K+p*16K (hi@+0, lo@+8K) = 80K total.
// q pre-scaled by 0.125.
// ============================================================================
#define QKV_XNH  0
#define QKV_XNL  16384
#define QKV_WT   32768
#define QKV_SMEM 81920

__global__ void __launch_bounds__(256) qkv_kernel(
        const float* __restrict__ x,
        const float* __restrict__ Wq, const float* __restrict__ bq,
        const float* __restrict__ Wk, const float* __restrict__ bk,
        const float* __restrict__ Wv, const float* __restrict__ bv,
        const float* __restrict__ gamma, const float* __restrict__ beta) {
    char* sm = dynsm;
    uint32_t smb = smem_u32(sm);
    int t = threadIdx.x, lane = t & 31, warp = t >> 5;
    int b = blockIdx.y, i0 = blockIdx.x * 128;

    // ---- W^T hi/lo into smem ([c][o] rows of 128B, SWZ) ----
    const float* Ws[3] = { Wq, Wk, Wv };
    #pragma unroll
    for (int p = 0; p < 3; p++) {
        const float* W = Ws[p];
        char* wb = sm + QKV_WT + p * 16384;
        for (int idx = t; idx < (C * C) / 4; idx += 256) {
            int o = idx >> 4, c4 = (idx & 15) * 4;
            float4 w = *(const float4*)(W + o * C + c4);
            const float* we = (const float*)&w;
            #pragma unroll
            for (int e = 0; e < 4; e++) {
                float wv = we[e];
                __nv_bfloat16 hi = __float2bfloat16(wv);
                __nv_bfloat16 lo = __float2bfloat16(wv - __bfloat162float(hi));
                uint32_t off = (uint32_t)((c4 + e) * 128 + o * 2);
                *(__nv_bfloat16*)(wb + SWZ(off))        = hi;
                *(__nv_bfloat16*)(wb + 8192 + SWZ(off)) = lo;
            }
        }
    }
    // ---- x tile: normalize, transpose to xn^T [i][c] hi/lo ----
    const float* xb = x + (size_t)b * C * NPIX;
    for (int idx = t; idx < C * 32; idx += 256) {
        int c = idx >> 5, i4 = (idx & 31) * 4;
        float4 v = *(const float4*)(xb + (size_t)c * NPIX + i0 + i4);
        int g = c >> 1;
        float mean = g_stats[(b * NGROUPS + g) * 2 + 0];
        float rstd = g_stats[(b * NGROUPS + g) * 2 + 1];
        float ga = gamma[c] * rstd, be = beta[c] - mean * ga;
        const float* ve = (const float*)&v;
        #pragma unroll
        for (int e = 0; e < 4; e++) {
            float xv = ve[e] * ga + be;
            __nv_bfloat16 hi = __float2bfloat16(xv);
            __nv_bfloat16 lo = __float2bfloat16(xv - __bfloat162float(hi));
            uint32_t off = (uint32_t)((i4 + e) * 128 + c * 2);
            *(__nv_bfloat16*)(sm + QKV_XNH + SWZ(off)) = hi;
            *(__nv_bfloat16*)(sm + QKV_XNL + SWZ(off)) = lo;
        }
    }
    __syncthreads();

    int mm = lane >> 3, r8 = lane & 7;
    int aRowB = (warp * 16 + (mm & 1) * 8 + r8) * 128;
    int aColB = (mm >> 1) * 16;
    int bKOff = (mm & 1) * 8 + r8;       // trans pattern (same as attn V)
    int bColB = (mm >> 1) * 16;

    uint32_t ah[4][4], al[4][4];
    #pragma unroll
    for (int kc = 0; kc < 4; kc++) {
        LDSM_X4(ah[kc], smb + QKV_XNH + SWZ((uint32_t)(aRowB + kc * 32 + aColB)));
        LDSM_X4(al[kc], smb + QKV_XNL + SWZ((uint32_t)(aRowB + kc * 32 + aColB)));
    }

    float Acc[3][8][4];
    #pragma unroll
    for (int p = 0; p < 3; p++)
        #pragma unroll
        for (int n8 = 0; n8 < 8; n8++)
            #pragma unroll
            for (int e = 0; e < 4; e++) Acc[p][n8][e] = 0.f;

    #pragma unroll
    for (int kc = 0; kc < 4; kc++) {
        #pragma unroll
        for (int p = 0; p < 3; p++) {
            uint32_t wbase = smb + QKV_WT + p * 16384;
            #pragma unroll
            for (int n16 = 0; n16 < 4; n16++) {
                uint32_t rowb = (uint32_t)((kc * 16 + bKOff) * 128 + n16 * 32 + bColB);
                uint32_t bh[4], bl[4];
                LDSM_X4T(bh, wbase + SWZ(rowb));
                MMA(Acc[p][2 * n16],     ah[kc], bh[0], bh[1]);
                MMA(Acc[p][2 * n16 + 1], ah[kc], bh[2], bh[3]);
                MMA(Acc[p][2 * n16],     al[kc], bh[0], bh[1]);
                MMA(Acc[p][2 * n16 + 1], al[kc], bh[2], bh[3]);
                LDSM_X4T(bl, wbase + 8192 + SWZ(rowb));
                MMA(Acc[p][2 * n16],     ah[kc], bl[0], bl[1]);
                MMA(Acc[p][2 * n16 + 1], ah[kc], bl[2], bl[3]);
            }
        }
    }

    // ---- epilogue: bias (+q scale), hi/lo split, packed stores ----
    __nv_bfloat16* hiA[3] = { g_qh, g_kh, g_vh };
    __nv_bfloat16* loA[3] = { g_ql, g_kl, g_vl };
    const float* biasA[3] = { bq, bk, bv };
    int r0 = warp * 16 + (lane >> 2);
    int ocol = (lane & 3) * 2;
    #pragma unroll
    for (int p = 0; p < 3; p++) {
        __nv_bfloat16* dh = hiA[p];
        __nv_bfloat16* dl = loA[p];
        #pragma unroll
        for (int n8 = 0; n8 < 8; n8++) {
            int o = n8 * 8 + ocol;
            float b0 = biasA[p][o], b1 = biasA[p][o + 1];
            #pragma unroll
            for (int hh = 0; hh < 2; hh++) {
                int i = r0 + hh * 8;
                float v0 = Acc[p][n8][2 * hh]     + b0;
                float v1 = Acc[p][n8][2 * hh + 1] + b1;
                if (p == 0) { v0 *= 0.125f; v1 *= 0.125f; }
                uint32_t h = pack_bf16x2(v0, v1);
                uint32_t l = pack_bf16x2(v0 - __uint_as_float(h << 16),
                                         v1 - __uint_as_float(h & 0xffff0000u));
                size_t ro = ((size_t)b * NPIX + i0 + i) * C + o;
                *(uint32_t*)(dh + ro) = h;
                *(uint32_t*)(dl + ro) = l;
            }
        }
    }
}

// ============================================================================
// K2: mma.sync bf16 flash attention + fused output projection/residual.
// (unchanged from R5 — at HMMA floor)
// ============================================================================
#define SM_QH    0
#define SM_QL    16384
#define SM_KV    32768
#define KVBUF    65536
#define KV_KH    0
#define KV_KL    16384
#define KV_VH    32768
#define KV_VL    49152
#define SM_ATTN  163840
#define WPAD     68

__device__ __forceinline__ void prefetch_kv(uint32_t smb, int buf, int j0,
        const uint4* kh4, const uint4* kl4, const uint4* vh4, const uint4* vl4, int t) {
    uint32_t base = smb + SM_KV + buf * KVBUF;
    #pragma unroll
    for (int q = 0; q < 4; q++) {
        int idx = t + q * 256;
        int row = idx >> 3, c16 = idx & 7;
        uint32_t sw = SWZ((uint32_t)(row * 128 + c16 * 16));
        size_t off = (size_t)(j0 + row) * 8 + c16;
        CP_ASYNC(base + KV_KH + sw, kh4 + off);
        CP_ASYNC(base + KV_KL + sw, kl4 + off);
        CP_ASYNC(base + KV_VH + sw, vh4 + off);
        CP_ASYNC(base + KV_VL + sw, vl4 + off);
    }
}

__global__ void __launch_bounds__(256) attn_kernel(
        const float* __restrict__ x, const float* __restrict__ Wo,
        const float* __restrict__ bo, float* __restrict__ out) {
    char* sm = dynsm;
    uint32_t smb = smem_u32(sm);
    int t = threadIdx.x, lane = t & 31, warp = t >> 5;
    int b = blockIdx.y, i0 = blockIdx.x * 128;

    const uint4* qh4 = (const uint4*)(g_qh + (size_t)b * NPIX * C);
    const uint4* ql4 = (const uint4*)(g_ql + (size_t)b * NPIX * C);
    const uint4* kh4 = (const uint4*)(g_kh + (size_t)b * NPIX * C);
    const uint4* kl4 = (const uint4*)(g_kl + (size_t)b * NPIX * C);
    const uint4* vh4 = (const uint4*)(g_vh + (size_t)b * NPIX * C);
    const uint4* vl4 = (const uint4*)(g_vl + (size_t)b * NPIX * C);

    for (int idx = t; idx < 2048; idx += 256) {
        int half = idx >> 10;
        int row = (idx & 1023) >> 3, c16 = idx & 7;
        uint32_t sw = SWZ((uint32_t)(row * 128 + c16 * 16));
        const uint4* src = half ? ql4 : qh4;
        *(uint4*)(sm + (half ? SM_QL : SM_QH) + sw) = src[(size_t)(i0 + row) * 8 + c16];
    }
    prefetch_kv(smb, 0, 0, kh4, kl4, vh4, vl4, t);
    CP_COMMIT;
    __syncthreads();

    int mm = lane >> 3, r8 = lane & 7;
    int qRowB  = (warp * 16 + (mm & 1) * 8 + r8) * 128;
    int qColB  = (mm >> 1) * 16;
    int kKeyOff = (mm >> 1) * 8 + r8;
    int kColB   = (mm & 1) * 16;
    int vKeyOff = (mm & 1) * 8 + r8;
    int vColB   = (mm >> 1) * 16;

    uint32_t qh[4][4], ql[4][4];
    #pragma unroll
    for (int kc = 0; kc < 4; kc++) {
        LDSM_X4(qh[kc], smb + SM_QH + SWZ((uint32_t)(qRowB + kc * 32 + qColB)));
        LDSM_X4(ql[kc], smb + SM_QL + SWZ((uint32_t)(qRowB + kc * 32 + qColB)));
    }

    float O[8][4];
    #pragma unroll
    for (int ct = 0; ct < 8; ct++)
        #pragma unroll
        for (int e = 0; e < 4; e++) O[ct][e] = 0.f;
    float l0 = 0.f, l1 = 0.f;

    for (int jb = 0; jb < 32; jb++) {
        if (jb + 1 < 32) {
            prefetch_kv(smb, (jb + 1) & 1, (jb + 1) * 128, kh4, kl4, vh4, vl4, t);
            CP_COMMIT;
            CP_WAIT1;
        } else {
            CP_WAIT0;
        }
        __syncthreads();
        uint32_t kvb = smb + SM_KV + (jb & 1) * KVBUF;

        float Sv[16][4];
        #pragma unroll
        for (int nt = 0; nt < 16; nt++)
            #pragma unroll
            for (int e = 0; e < 4; e++) Sv[nt][e] = 0.f;

        #pragma unroll
        for (int kc = 0; kc < 4; kc++) {
            #pragma unroll
            for (int ntp = 0; ntp < 8; ntp++) {
                uint32_t rowb = (uint32_t)((ntp * 16 + kKeyOff) * 128 + kc * 32 + kColB);
                uint32_t bh[4], bl[4];
                LDSM_X4(bh, kvb + KV_KH + SWZ(rowb));
                MMA(Sv[2 * ntp],     qh[kc], bh[0], bh[1]);
                MMA(Sv[2 * ntp + 1], qh[kc], bh[2], bh[3]);
                MMA(Sv[2 * ntp],     ql[kc], bh[0], bh[1]);
                MMA(Sv[2 * ntp + 1], ql[kc], bh[2], bh[3]);
                LDSM_X4(bl, kvb + KV_KL + SWZ(rowb));
                MMA(Sv[2 * ntp],     qh[kc], bl[0], bl[1]);
                MMA(Sv[2 * ntp + 1], qh[kc], bl[2], bl[3]);
            }
        }

        float rs0 = 0.f, rs1 = 0.f;
        #pragma unroll
        for (int nt = 0; nt < 16; nt++) {
            Sv[nt][0] = __expf(Sv[nt][0]);
            Sv[nt][1] = __expf(Sv[nt][1]);
            Sv[nt][2] = __expf(Sv[nt][2]);
            Sv[nt][3] = __expf(Sv[nt][3]);
            rs0 += Sv[nt][0] + Sv[nt][1];
            rs1 += Sv[nt][2] + Sv[nt][3];
        }
        rs0 += __shfl_xor_sync(0xffffffffu, rs0, 1);
        rs0 += __shfl_xor_sync(0xffffffffu, rs0, 2);
        rs1 += __shfl_xor_sync(0xffffffffu, rs1, 1);
        rs1 += __shfl_xor_sync(0xffffffffu, rs1, 2);
        l0 += rs0; l1 += rs1;

        #pragma unroll
        for (int kk = 0; kk < 8; kk++) {
            uint32_t ph[4], pl[4];
            #pragma unroll
            for (int h = 0; h < 2; h++) {
                float s0 = Sv[2 * kk + h][0], s1 = Sv[2 * kk + h][1];
                float s2 = Sv[2 * kk + h][2], s3 = Sv[2 * kk + h][3];
                uint32_t h01 = pack_bf16x2(s0, s1);
                uint32_t h23 = pack_bf16x2(s2, s3);
                ph[2 * h]     = h01;
                ph[2 * h + 1] = h23;
                pl[2 * h]     = pack_bf16x2(s0 - __uint_as_float(h01 << 16),
                                            s1 - __uint_as_float(h01 & 0xffff0000u));
                pl[2 * h + 1] = pack_bf16x2(s2 - __uint_as_float(h23 << 16),
                                            s3 - __uint_as_float(h23 & 0xffff0000u));
            }
            #pragma unroll
            for (int ctp = 0; ctp < 4; ctp++) {
                uint32_t rowb = (uint32_t)((kk * 16 + vKeyOff) * 128 + ctp * 32 + vColB);
                uint32_t bh[4], bl[4];
                LDSM_X4T(bh, kvb + KV_VH + SWZ(rowb));
                MMA(O[2 * ctp],     ph, bh[0], bh[1]);
                MMA(O[2 * ctp + 1], ph, bh[2], bh[3]);
                MMA(O[2 * ctp],     pl, bh[0], bh[1]);
                MMA(O[2 * ctp + 1], pl, bh[2], bh[3]);
                LDSM_X4T(bl, kvb + KV_VL + SWZ(rowb));
                MMA(O[2 * ctp],     ph, bl[0], bl[1]);
                MMA(O[2 * ctp + 1], ph, bl[2], bl[3]);
            }
        }
        __syncthreads();
    }

    float* ws = (float*)(sm + SM_QH);
    for (int idx = t; idx < C * C; idx += 256) {
        int oo = idx >> 6, cc = idx & 63;
        ws[cc * WPAD + oo] = Wo[idx];
    }
    float inv0 = 1.f / l0, inv1 = 1.f / l1;
    float* sO = (float*)(sm + SM_KV);
    int r = warp * 16 + (lane >> 2);
    #pragma unroll
    for (int ct = 0; ct < 8; ct++) {
        int ch = ct * 8 + (lane & 3) * 2;
        sO[ch * XPAD + r]           = O[ct][0] * inv0;
        sO[(ch + 1) * XPAD + r]     = O[ct][1] * inv0;
        sO[ch * XPAD + r + 8]       = O[ct][2] * inv1;
        sO[(ch + 1) * XPAD + r + 8] = O[ct][3] * inv1;
    }
    __syncthreads();

    int tx = t & 15, ty = t >> 4;
    int oo = ty * 4, ii = tx * 8;
    float acc[4][8];
    #pragma unroll
    for (int rr = 0; rr < 4; rr++)
        #pragma unroll
        for (int s = 0; s < 8; s++) acc[rr][s] = 0.f;

    #pragma unroll 4
    for (int c = 0; c < C; c++) {
        float xf[8], wf[4];
        *(float4*)(xf)     = *(const float4*)(sO + c * XPAD + ii);
        *(float4*)(xf + 4) = *(const float4*)(sO + c * XPAD + ii + 4);
        *(float4*)(wf)     = *(const float4*)(ws + c * WPAD + oo);
        #pragma unroll
        for (int rr = 0; rr < 4; rr++)
            #pragma unroll
            for (int s = 0; s < 8; s++) acc[rr][s] += wf[rr] * xf[s];
    }
    #pragma unroll
    for (int rr = 0; rr < 4; rr++) {
        int o = oo + rr;
        float bv = bo[o];
        size_t off = ((size_t)(b * C + o)) * NPIX + i0 + ii;
        float4 x0 = *(const float4*)(x + off);
        float4 x1 = *(const float4*)(x + off + 4);
        float tmp[8];
        tmp[0] = x0.x + acc[rr][0] + bv; tmp[1] = x0.y + acc[rr][1] + bv;
        tmp[2] = x0.z + acc[rr][2] + bv; tmp[3] = x0.w + acc[rr][3] + bv;
        tmp[4] = x1.x + acc[rr][4] + bv; tmp[5] = x1.y + acc[rr][5] + bv;
        tmp[6] = x1.z + acc[rr][6] + bv; tmp[7] = x1.w + acc[rr][7] + bv;
        *(float4*)(out + off)     = *(float4*)tmp;
        *(float4*)(out + off + 4) = *(float4*)(tmp + 4);
    }
}

// ============================================================================
extern "C" void kernel_launch(void* const* d_in, const int* in_sizes, int n_in,
                              void* d_out, int out_size) {
    const float* x     = (const float*)d_in[0];
    const float* Wq    = (const float*)d_in[1];
    const float* bq    = (const float*)d_in[2];
    const float* Wk    = (const float*)d_in[3];
    const float* bk    = (const float*)d_in[4];
    const float* Wv    = (const float*)d_in[5];
    const float* bv    = (const float*)d_in[6];
    const float* Wo    = (const float*)d_in[7];
    const float* bo    = (const float*)d_in[8];
    const float* gamma = (const float*)d_in[9];
    const float* beta  = (const float*)d_in[10];
    float* out = (float*)d_out;

    cudaFuncSetAttribute(qkv_kernel,  cudaFuncAttributeMaxDynamicSharedMemorySize, QKV_SMEM);
    cudaFuncSetAttribute(attn_kernel, cudaFuncAttributeMaxDynamicSharedMemorySize, SM_ATTN);

    gn_stats_kernel<<<dim3(NGROUPS, BATCH), 512>>>(x);
    qkv_kernel<<<dim3(NPIX / 128, BATCH), 256, QKV_SMEM>>>(x, Wq, bq, Wk, bk, Wv, bv, gamma, beta);
    attn_kernel<<<dim3(NPIX / 128, BATCH), 256, SM_ATTN>>>(x, Wo, bo, out);
}

// round 7
// speedup vs baseline: 1.5318x; 1.5318x over previous
#include <cuda_runtime.h>
#include <cuda_bf16.h>
#include <cstdint>
#include <cstddef>

#define BATCH   4
#define C       64
#define NPIX    4096
#define NGROUPS 32
#define WPAD    68
#define XPAD    132

// ---------------- scratch (device globals; no runtime allocation) ------------
__device__ __nv_bfloat16 g_qh[BATCH * NPIX * C];   // [b][n][c] rows of 128B
__device__ __nv_bfloat16 g_ql[BATCH * NPIX * C];
__device__ __nv_bfloat16 g_kh[BATCH * NPIX * C];
__device__ __nv_bfloat16 g_kl[BATCH * NPIX * C];
__device__ __nv_bfloat16 g_vh[BATCH * NPIX * C];
__device__ __nv_bfloat16 g_vl[BATCH * NPIX * C];
__device__ float         g_stats[BATCH * NGROUPS * 2];

extern __shared__ char dynsm[];

// ---------------- helpers ----------------------------------------------------
__device__ __forceinline__ uint32_t smem_u32(const void* p) {
    uint32_t a;
    asm("{ .reg .u64 t; cvta.to.shared.u64 t, %1; cvt.u32.u64 %0, t; }" : "=r"(a) : "l"(p));
    return a;
}
#define SWZ(o) ((o) ^ (((o) >> 3) & 0x70))

#define CP_ASYNC(dst, src) \
    asm volatile("cp.async.cg.shared.global [%0], [%1], 16;" :: "r"(dst), "l"(src) : "memory")
#define CP_COMMIT asm volatile("cp.async.commit_group;" ::: "memory")
#define CP_WAIT1  asm volatile("cp.async.wait_group 1;" ::: "memory")
#define CP_WAIT0  asm volatile("cp.async.wait_group 0;" ::: "memory")

#define LDSM_X4(r, a) \
    asm volatile("ldmatrix.sync.aligned.m8n8.x4.shared.b16 {%0,%1,%2,%3}, [%4];" \
        : "=r"((r)[0]), "=r"((r)[1]), "=r"((r)[2]), "=r"((r)[3]) : "r"(a))
#define LDSM_X4T(r, a) \
    asm volatile("ldmatrix.sync.aligned.m8n8.x4.trans.shared.b16 {%0,%1,%2,%3}, [%4];" \
        : "=r"((r)[0]), "=r"((r)[1]), "=r"((r)[2]), "=r"((r)[3]) : "r"(a))

// D += A * B  (m16n8k16, bf16 in, f32 accum)
#define MMA(c, a, b0, b1) \
    asm volatile("mma.sync.aligned.m16n8k16.row.col.f32.bf16.bf16.f32 " \
        "{%0,%1,%2,%3}, {%4,%5,%6,%7}, {%8,%9}, {%0,%1,%2,%3};" \
        : "+f"((c)[0]), "+f"((c)[1]), "+f"((c)[2]), "+f"((c)[3]) \
        : "r"((a)[0]), "r"((a)[1]), "r"((a)[2]), "r"((a)[3]), "r"(b0), "r"(b1))

__device__ __forceinline__ uint32_t pack_bf16x2(float lo, float hi) {
    uint32_t r;
    asm("cvt.rn.bf16x2.f32 %0, %1, %2;" : "=r"(r) : "f"(hi), "f"(lo));
    return r;
}

// ============================================================================
// K0: GroupNorm statistics (512 threads)
// ============================================================================
__global__ void __launch_bounds__(512) gn_stats_kernel(const float* __restrict__ x) {
    int g = blockIdx.x, b = blockIdx.y;
    const float* base = x + ((size_t)b * C + (size_t)g * 2) * NPIX;
    float s = 0.f, s2 = 0.f;
    const float4* p4 = (const float4*)base;
    for (int idx = threadIdx.x; idx < (2 * NPIX) / 4; idx += blockDim.x) {
        float4 v = p4[idx];
        s  += v.x + v.y + v.z + v.w;
        s2 += v.x * v.x + v.y * v.y + v.z * v.z + v.w * v.w;
    }
    __shared__ float rs[32], rs2[32];
    #pragma unroll
    for (int o = 16; o; o >>= 1) {
        s  += __shfl_xor_sync(0xffffffffu, s,  o);
        s2 += __shfl_xor_sync(0xffffffffu, s2, o);
    }
    int lane = threadIdx.x & 31, w = threadIdx.x >> 5;
    if (lane == 0) { rs[w] = s; rs2[w] = s2; }
    __syncthreads();
    if (w == 0) {
        s  = (lane < (int)(blockDim.x >> 5)) ? rs[lane]  : 0.f;
        s2 = (lane < (int)(blockDim.x >> 5)) ? rs2[lane] : 0.f;
        #pragma unroll
        for (int o = 16; o; o >>= 1) {
            s  += __shfl_xor_sync(0xffffffffu, s,  o);
            s2 += __shfl_xor_sync(0xffffffffu, s2, o);
        }
        if (lane == 0) {
            const float invn = 1.f / (2.f * NPIX);
            float mean = s * invn;
            float var  = s2 * invn - mean * mean;
            g_stats[(b * NGROUPS + g) * 2 + 0] = mean;
            g_stats[(b * NGROUPS + g) * 2 + 1] = rsqrtf(var + 1e-5f);
        }
    }
}

// ============================================================================
// K1: GroupNorm-apply + QKV projection (R5 FFMA structure, 512 threads).
// NEW: epilogue stages hi/lo words through padded smem and writes global
// as fully-coalesced 128B warp stores (was: 48 scattered 4B stores/thread).
// q pre-scaled by 1/sqrt(C) = 0.125.
// ============================================================================
__global__ void __launch_bounds__(512) qkv_kernel(
                           const float* __restrict__ x,
                           const float* __restrict__ Wq, const float* __restrict__ bq,
                           const float* __restrict__ Wk, const float* __restrict__ bk,
                           const float* __restrict__ Wv, const float* __restrict__ bv,
                           const float* __restrict__ gamma, const float* __restrict__ beta) {
    float* smf = (float*)dynsm;
    float* wqs = smf;
    float* wks = wqs + C * WPAD;
    float* wvs = wks + C * WPAD;
    float* xns = wvs + C * WPAD;
    int t = threadIdx.x, b = blockIdx.y, i0 = blockIdx.x * 128;

    for (int idx = t; idx < C * C; idx += 512) {
        int oo = idx >> 6, cc = idx & 63;
        wqs[cc * WPAD + oo] = Wq[idx];
        wks[cc * WPAD + oo] = Wk[idx];
        wvs[cc * WPAD + oo] = Wv[idx];
    }
    const float* xb = x + (size_t)b * C * NPIX;
    for (int idx = t; idx < C * 32; idx += 512) {
        int c = idx >> 5, i4 = idx & 31;
        float4 v = *(const float4*)(xb + (size_t)c * NPIX + i0 + i4 * 4);
        int g = c >> 1;
        float mean = g_stats[(b * NGROUPS + g) * 2 + 0];
        float rstd = g_stats[(b * NGROUPS + g) * 2 + 1];
        float ga = gamma[c] * rstd;
        float be = beta[c] - mean * ga;
        v.x = v.x * ga + be; v.y = v.y * ga + be;
        v.z = v.z * ga + be; v.w = v.w * ga + be;
        *(float4*)(xns + c * XPAD + i4 * 4) = v;
    }
    __syncthreads();

    int tx = t & 15, ty = t >> 4;          // ty in [0,32): channel pair
    int oo = ty * 2, ii = tx * 8;
    float aq[2][8], ak[2][8], av[2][8];
    #pragma unroll
    for (int r = 0; r < 2; r++)
        #pragma unroll
        for (int s = 0; s < 8; s++) { aq[r][s] = 0.f; ak[r][s] = 0.f; av[r][s] = 0.f; }

    #pragma unroll 4
    for (int c = 0; c < C; c++) {
        float xf[8];
        *(float4*)(xf)     = *(const float4*)(xns + c * XPAD + ii);
        *(float4*)(xf + 4) = *(const float4*)(xns + c * XPAD + ii + 4);
        float2 wq2 = *(const float2*)(wqs + c * WPAD + oo);
        float2 wk2 = *(const float2*)(wks + c * WPAD + oo);
        float2 wv2 = *(const float2*)(wvs + c * WPAD + oo);
        #pragma unroll
        for (int s = 0; s < 8; s++) {
            aq[0][s] += wq2.x * xf[s];  aq[1][s] += wq2.y * xf[s];
            ak[0][s] += wk2.x * xf[s];  ak[1][s] += wk2.y * xf[s];
            av[0][s] += wv2.x * xf[s];  av[1][s] += wv2.y * xf[s];
        }
    }

    float bi0[3], bi1[3];
    bi0[0] = bq[oo]; bi1[0] = bq[oo + 1];
    bi0[1] = bk[oo]; bi1[1] = bk[oo + 1];
    bi0[2] = bv[oo]; bi1[2] = bv[oo + 1];

    // ---- staged, coalesced epilogue ----
    // buffers reuse the w regions (all reads of w/xns are done after sync)
    uint32_t* bufh = (uint32_t*)smf;            // [128][33] words
    uint32_t* bufl = bufh + 128 * 33;           // [128][33] words (ends @33792B < 52224B)
    int cw = t & 31, pg = t >> 5;               // copy-out mapping

    #pragma unroll
    for (int p = 0; p < 3; p++) {
        __syncthreads();                        // prev round copy-out done / compute done
        #pragma unroll
        for (int s = 0; s < 8; s++) {
            float v0 = (p == 0 ? aq[0][s] : p == 1 ? ak[0][s] : av[0][s]) + bi0[p];
            float v1 = (p == 0 ? aq[1][s] : p == 1 ? ak[1][s] : av[1][s]) + bi1[p];
            if (p == 0) { v0 *= 0.125f; v1 *= 0.125f; }
            uint32_t h = pack_bf16x2(v0, v1);
            uint32_t l = pack_bf16x2(v0 - __uint_as_float(h << 16),
                                     v1 - __uint_as_float(h & 0xffff0000u));
            int pix = ii + s;
            bufh[pix * 33 + ty] = h;
            bufl[pix * 33 + ty] = l;
        }
        __syncthreads();
        __nv_bfloat16* dh = (p == 0) ? g_qh : (p == 1) ? g_kh : g_vh;
        __nv_bfloat16* dl = (p == 0) ? g_ql : (p == 1) ? g_kl : g_vl;
        uint32_t* gh = (uint32_t*)(dh + ((size_t)b * NPIX + i0) * C);
        uint32_t* gl = (uint32_t*)(dl + ((size_t)b * NPIX + i0) * C);
        #pragma unroll
        for (int e = 0; e < 8; e++) {
            int pix = pg * 8 + e;
            gh[pix * 32 + cw] = bufh[pix * 33 + cw];
            gl[pix * 32 + cw] = bufl[pix * 33 + cw];
        }
    }
}

// ============================================================================
// K2: mma.sync bf16 flash attention + fused output projection/residual.
// (R5 version — at the measured HMMA issue floor)
// ============================================================================
#define SM_QH    0
#define SM_QL    16384
#define SM_KV    32768
#define KVBUF    65536
#define KV_KH    0
#define KV_KL    16384
#define KV_VH    32768
#define KV_VL    49152
#define SM_ATTN  163840

__device__ __forceinline__ void prefetch_kv(uint32_t smb, int buf, int j0,
        const uint4* kh4, const uint4* kl4, const uint4* vh4, const uint4* vl4, int t) {
    uint32_t base = smb + SM_KV + buf * KVBUF;
    #pragma unroll
    for (int q = 0; q < 4; q++) {
        int idx = t + q * 256;
        int row = idx >> 3, c16 = idx & 7;
        uint32_t sw = SWZ((uint32_t)(row * 128 + c16 * 16));
        size_t off = (size_t)(j0 + row) * 8 + c16;
        CP_ASYNC(base + KV_KH + sw, kh4 + off);
        CP_ASYNC(base + KV_KL + sw, kl4 + off);
        CP_ASYNC(base + KV_VH + sw, vh4 + off);
        CP_ASYNC(base + KV_VL + sw, vl4 + off);
    }
}

__global__ void __launch_bounds__(256) attn_kernel(
        const float* __restrict__ x, const float* __restrict__ Wo,
        const float* __restrict__ bo, float* __restrict__ out) {
    char* sm = dynsm;
    uint32_t smb = smem_u32(sm);
    int t = threadIdx.x, lane = t & 31, warp = t >> 5;
    int b = blockIdx.y, i0 = blockIdx.x * 128;

    const uint4* qh4 = (const uint4*)(g_qh + (size_t)b * NPIX * C);
    const uint4* ql4 = (const uint4*)(g_ql + (size_t)b * NPIX * C);
    const uint4* kh4 = (const uint4*)(g_kh + (size_t)b * NPIX * C);
    const uint4* kl4 = (const uint4*)(g_kl + (size_t)b * NPIX * C);
    const uint4* vh4 = (const uint4*)(g_vh + (size_t)b * NPIX * C);
    const uint4* vl4 = (const uint4*)(g_vl + (size_t)b * NPIX * C);

    for (int idx = t; idx < 2048; idx += 256) {
        int half = idx >> 10;
        int row = (idx & 1023) >> 3, c16 = idx & 7;
        uint32_t sw = SWZ((uint32_t)(row * 128 + c16 * 16));
        const uint4* src = half ? ql4 : qh4;
        *(uint4*)(sm + (half ? SM_QL : SM_QH) + sw) = src[(size_t)(i0 + row) * 8 + c16];
    }
    prefetch_kv(smb, 0, 0, kh4, kl4, vh4, vl4, t);
    CP_COMMIT;
    __syncthreads();

    int mm = lane >> 3, r8 = lane & 7;
    int qRowB  = (warp * 16 + (mm & 1) * 8 + r8) * 128;
    int qColB  = (mm >> 1) * 16;
    int kKeyOff = (mm >> 1) * 8 + r8;
    int kColB   = (mm & 1) * 16;
    int vKeyOff = (mm & 1) * 8 + r8;
    int vColB   = (mm >> 1) * 16;

    uint32_t qh[4][4], ql[4][4];
    #pragma unroll
    for (int kc = 0; kc < 4; kc++) {
        LDSM_X4(qh[kc], smb + SM_QH + SWZ((uint32_t)(qRowB + kc * 32 + qColB)));
        LDSM_X4(ql[kc], smb + SM_QL + SWZ((uint32_t)(qRowB + kc * 32 + qColB)));
    }

    float O[8][4];
    #pragma unroll
    for (int ct = 0; ct < 8; ct++)
        #pragma unroll
        for (int e = 0; e < 4; e++) O[ct][e] = 0.f;
    float l0 = 0.f, l1 = 0.f;

    for (int jb = 0; jb < 32; jb++) {
        if (jb + 1 < 32) {
            prefetch_kv(smb, (jb + 1) & 1, (jb + 1) * 128, kh4, kl4, vh4, vl4, t);
            CP_COMMIT;
            CP_WAIT1;
        } else {
            CP_WAIT0;
        }
        __syncthreads();
        uint32_t kvb = smb + SM_KV + (jb & 1) * KVBUF;

        float Sv[16][4];
        #pragma unroll
        for (int nt = 0; nt < 16; nt++)
            #pragma unroll
            for (int e = 0; e < 4; e++) Sv[nt][e] = 0.f;

        #pragma unroll
        for (int kc = 0; kc < 4; kc++) {
            #pragma unroll
            for (int ntp = 0; ntp < 8; ntp++) {
                uint32_t rowb = (uint32_t)((ntp * 16 + kKeyOff) * 128 + kc * 32 + kColB);
                uint32_t bh[4], bl[4];
                LDSM_X4(bh, kvb + KV_KH + SWZ(rowb));
                MMA(Sv[2 * ntp],     qh[kc], bh[0], bh[1]);
                MMA(Sv[2 * ntp + 1], qh[kc], bh[2], bh[3]);
                MMA(Sv[2 * ntp],     ql[kc], bh[0], bh[1]);
                MMA(Sv[2 * ntp + 1], ql[kc], bh[2], bh[3]);
                LDSM_X4(bl, kvb + KV_KL + SWZ(rowb));
                MMA(Sv[2 * ntp],     qh[kc], bl[0], bl[1]);
                MMA(Sv[2 * ntp + 1], qh[kc], bl[2], bl[3]);
            }
        }

        float rs0 = 0.f, rs1 = 0.f;
        #pragma unroll
        for (int nt = 0; nt < 16; nt++) {
            Sv[nt][0] = __expf(Sv[nt][0]);
            Sv[nt][1] = __expf(Sv[nt][1]);
            Sv[nt][2] = __expf(Sv[nt][2]);
            Sv[nt][3] = __expf(Sv[nt][3]);
            rs0 += Sv[nt][0] + Sv[nt][1];
            rs1 += Sv[nt][2] + Sv[nt][3];
        }
        rs0 += __shfl_xor_sync(0xffffffffu, rs0, 1);
        rs0 += __shfl_xor_sync(0xffffffffu, rs0, 2);
        rs1 += __shfl_xor_sync(0xffffffffu, rs1, 1);
        rs1 += __shfl_xor_sync(0xffffffffu, rs1, 2);
        l0 += rs0; l1 += rs1;

        #pragma unroll
        for (int kk = 0; kk < 8; kk++) {
            uint32_t ph[4], pl[4];
            #pragma unroll
            for (int h = 0; h < 2; h++) {
                float s0 = Sv[2 * kk + h][0], s1 = Sv[2 * kk + h][1];
                float s2 = Sv[2 * kk + h][2], s3 = Sv[2 * kk + h][3];
                uint32_t h01 = pack_bf16x2(s0, s1);
                uint32_t h23 = pack_bf16x2(s2, s3);
                ph[2 * h]     = h01;
                ph[2 * h + 1] = h23;
                pl[2 * h]     = pack_bf16x2(s0 - __uint_as_float(h01 << 16),
                                            s1 - __uint_as_float(h01 & 0xffff0000u));
                pl[2 * h + 1] = pack_bf16x2(s2 - __uint_as_float(h23 << 16),
                                            s3 - __uint_as_float(h23 & 0xffff0000u));
            }
            #pragma unroll
            for (int ctp = 0; ctp < 4; ctp++) {
                uint32_t rowb = (uint32_t)((kk * 16 + vKeyOff) * 128 + ctp * 32 + vColB);
                uint32_t bh[4], bl[4];
                LDSM_X4T(bh, kvb + KV_VH + SWZ(rowb));
                MMA(O[2 * ctp],     ph, bh[0], bh[1]);
                MMA(O[2 * ctp + 1], ph, bh[2], bh[3]);
                MMA(O[2 * ctp],     pl, bh[0], bh[1]);
                MMA(O[2 * ctp + 1], pl, bh[2], bh[3]);
                LDSM_X4T(bl, kvb + KV_VL + SWZ(rowb));
                MMA(O[2 * ctp],     ph, bl[0], bl[1]);
                MMA(O[2 * ctp + 1], ph, bl[2], bl[3]);
            }
        }
        __syncthreads();
    }

    float* ws = (float*)(sm + SM_QH);
    for (int idx = t; idx < C * C; idx += 256) {
        int oo = idx >> 6, cc = idx & 63;
        ws[cc * WPAD + oo] = Wo[idx];
    }
    float inv0 = 1.f / l0, inv1 = 1.f / l1;
    float* sO = (float*)(sm + SM_KV);
    int r = warp * 16 + (lane >> 2);
    #pragma unroll
    for (int ct = 0; ct < 8; ct++) {
        int ch = ct * 8 + (lane & 3) * 2;
        sO[ch * XPAD + r]           = O[ct][0] * inv0;
        sO[(ch + 1) * XPAD + r]     = O[ct][1] * inv0;
        sO[ch * XPAD + r + 8]       = O[ct][2] * inv1;
        sO[(ch + 1) * XPAD + r + 8] = O[ct][3] * inv1;
    }
    __syncthreads();

    int tx = t & 15, ty = t >> 4;
    int oo = ty * 4, ii = tx * 8;
    float acc[4][8];
    #pragma unroll
    for (int rr = 0; rr < 4; rr++)
        #pragma unroll
        for (int s = 0; s < 8; s++) acc[rr][s] = 0.f;

    #pragma unroll 4
    for (int c = 0; c < C; c++) {
        float xf[8], wf[4];
        *(float4*)(xf)     = *(const float4*)(sO + c * XPAD + ii);
        *(float4*)(xf + 4) = *(const float4*)(sO + c * XPAD + ii + 4);
        *(float4*)(wf)     = *(const float4*)(ws + c * WPAD + oo);
        #pragma unroll
        for (int rr = 0; rr < 4; rr++)
            #pragma unroll
            for (int s = 0; s < 8; s++) acc[rr][s] += wf[rr] * xf[s];
    }
    #pragma unroll
    for (int rr = 0; rr < 4; rr++) {
        int o = oo + rr;
        float bv = bo[o];
        size_t off = ((size_t)(b * C + o)) * NPIX + i0 + ii;
        float4 x0 = *(const float4*)(x + off);
        float4 x1 = *(const float4*)(x + off + 4);
        float tmp[8];
        tmp[0] = x0.x + acc[rr][0] + bv; tmp[1] = x0.y + acc[rr][1] + bv;
        tmp[2] = x0.z + acc[rr][2] + bv; tmp[3] = x0.w + acc[rr][3] + bv;
        tmp[4] = x1.x + acc[rr][4] + bv; tmp[5] = x1.y + acc[rr][5] + bv;
        tmp[6] = x1.z + acc[rr][6] + bv; tmp[7] = x1.w + acc[rr][7] + bv;
        *(float4*)(out + off)     = *(float4*)tmp;
        *(float4*)(out + off + 4) = *(float4*)(tmp + 4);
    }
}

// ============================================================================
extern "C" void kernel_launch(void* const* d_in, const int* in_sizes, int n_in,
                              void* d_out, int out_size) {
    const float* x     = (const float*)d_in[0];
    const float* Wq    = (const float*)d_in[1];
    const float* bq    = (const float*)d_in[2];
    const float* Wk    = (const float*)d_in[3];
    const float* bk    = (const float*)d_in[4];
    const float* Wv    = (const float*)d_in[5];
    const float* bv    = (const float*)d_in[6];
    const float* Wo    = (const float*)d_in[7];
    const float* bo    = (const float*)d_in[8];
    const float* gamma = (const float*)d_in[9];
    const float* beta  = (const float*)d_in[10];
    float* out = (float*)d_out;

    const int QKV_SMEM = (3 * C * WPAD + C * XPAD) * 4;

    cudaFuncSetAttribute(qkv_kernel,  cudaFuncAttributeMaxDynamicSharedMemorySize, QKV_SMEM);
    cudaFuncSetAttribute(attn_kernel, cudaFuncAttributeMaxDynamicSharedMemorySize, SM_ATTN);

    gn_stats_kernel<<<dim3(NGROUPS, BATCH), 512>>>(x);
    qkv_kernel<<<dim3(NPIX / 128, BATCH), 512, QKV_SMEM>>>(x, Wq, bq, Wk, bk, Wv, bv, gamma, beta);
    attn_kernel<<<dim3(NPIX / 128, BATCH), 256, SM_ATTN>>>(x, Wo, bo, out);
}

// round 8
// speedup vs baseline: 1.9826x; 1.2943x over previous
#include <cuda_runtime.h>
#include <cuda_bf16.h>
#include <cstdint>
#include <cstddef>

#define BATCH   4
#define C       64
#define NPIX    4096
#define NGROUPS 32
#define WPAD    68
#define XPAD    132

// ---------------- scratch (device globals; no runtime allocation) ------------
__device__ __nv_bfloat16 g_qh[BATCH * NPIX * C];   // [b][n][c] rows of 128B
__device__ __nv_bfloat16 g_kh[BATCH * NPIX * C];
__device__ __nv_bfloat16 g_kl[BATCH * NPIX * C];
__device__ __nv_bfloat16 g_vh[BATCH * NPIX * C];
__device__ __nv_bfloat16 g_vl[BATCH * NPIX * C];
__device__ float         g_stats[BATCH * NGROUPS * 2];

extern __shared__ char dynsm[];

// ---------------- helpers ----------------------------------------------------
__device__ __forceinline__ uint32_t smem_u32(const void* p) {
    uint32_t a;
    asm("{ .reg .u64 t; cvta.to.shared.u64 t, %1; cvt.u32.u64 %0, t; }" : "=r"(a) : "l"(p));
    return a;
}
#define SWZ(o) ((o) ^ (((o) >> 3) & 0x70))

#define CP_ASYNC(dst, src) \
    asm volatile("cp.async.cg.shared.global [%0], [%1], 16;" :: "r"(dst), "l"(src) : "memory")
#define CP_COMMIT asm volatile("cp.async.commit_group;" ::: "memory")
#define CP_WAIT1  asm volatile("cp.async.wait_group 1;" ::: "memory")
#define CP_WAIT0  asm volatile("cp.async.wait_group 0;" ::: "memory")

#define LDSM_X4(r, a) \
    asm volatile("ldmatrix.sync.aligned.m8n8.x4.shared.b16 {%0,%1,%2,%3}, [%4];" \
        : "=r"((r)[0]), "=r"((r)[1]), "=r"((r)[2]), "=r"((r)[3]) : "r"(a))
#define LDSM_X4T(r, a) \
    asm volatile("ldmatrix.sync.aligned.m8n8.x4.trans.shared.b16 {%0,%1,%2,%3}, [%4];" \
        : "=r"((r)[0]), "=r"((r)[1]), "=r"((r)[2]), "=r"((r)[3]) : "r"(a))

// D += A * B  (m16n8k16, bf16 in, f32 accum)
#define MMA(c, a, b0, b1) \
    asm volatile("mma.sync.aligned.m16n8k16.row.col.f32.bf16.bf16.f32 " \
        "{%0,%1,%2,%3}, {%4,%5,%6,%7}, {%8,%9}, {%0,%1,%2,%3};" \
        : "+f"((c)[0]), "+f"((c)[1]), "+f"((c)[2]), "+f"((c)[3]) \
        : "r"((a)[0]), "r"((a)[1]), "r"((a)[2]), "r"((a)[3]), "r"(b0), "r"(b1))

__device__ __forceinline__ uint32_t pack_bf16x2(float lo, float hi) {
    uint32_t r;
    asm("cvt.rn.bf16x2.f32 %0, %1, %2;" : "=r"(r) : "f"(hi), "f"(lo));
    return r;
}

// ============================================================================
// K0: GroupNorm statistics (512 threads)
// ============================================================================
__global__ void __launch_bounds__(512) gn_stats_kernel(const float* __restrict__ x) {
    int g = blockIdx.x, b = blockIdx.y;
    const float* base = x + ((size_t)b * C + (size_t)g * 2) * NPIX;
    float s = 0.f, s2 = 0.f;
    const float4* p4 = (const float4*)base;
    for (int idx = threadIdx.x; idx < (2 * NPIX) / 4; idx += blockDim.x) {
        float4 v = p4[idx];
        s  += v.x + v.y + v.z + v.w;
        s2 += v.x * v.x + v.y * v.y + v.z * v.z + v.w * v.w;
    }
    __shared__ float rs[32], rs2[32];
    #pragma unroll
    for (int o = 16; o; o >>= 1) {
        s  += __shfl_xor_sync(0xffffffffu, s,  o);
        s2 += __shfl_xor_sync(0xffffffffu, s2, o);
    }
    int lane = threadIdx.x & 31, w = threadIdx.x >> 5;
    if (lane == 0) { rs[w] = s; rs2[w] = s2; }
    __syncthreads();
    if (w == 0) {
        s  = (lane < (int)(blockDim.x >> 5)) ? rs[lane]  : 0.f;
        s2 = (lane < (int)(blockDim.x >> 5)) ? rs2[lane] : 0.f;
        #pragma unroll
        for (int o = 16; o; o >>= 1) {
            s  += __shfl_xor_sync(0xffffffffu, s,  o);
            s2 += __shfl_xor_sync(0xffffffffu, s2, o);
        }
        if (lane == 0) {
            const float invn = 1.f / (2.f * NPIX);
            float mean = s * invn;
            float var  = s2 * invn - mean * mean;
            g_stats[(b * NGROUPS + g) * 2 + 0] = mean;
            g_stats[(b * NGROUPS + g) * 2 + 1] = rsqrtf(var + 1e-5f);
        }
    }
}

// ============================================================================
// K1: GroupNorm-apply + QKV projection (512 threads, staged coalesced stores).
// q emits bf16 hi only (attn uses 2-term S); k, v emit hi/lo.
// q pre-scaled by 1/sqrt(C) = 0.125.
// ============================================================================
__global__ void __launch_bounds__(512) qkv_kernel(
                           const float* __restrict__ x,
                           const float* __restrict__ Wq, const float* __restrict__ bq,
                           const float* __restrict__ Wk, const float* __restrict__ bk,
                           const float* __restrict__ Wv, const float* __restrict__ bv,
                           const float* __restrict__ gamma, const float* __restrict__ beta) {
    float* smf = (float*)dynsm;
    float* wqs = smf;
    float* wks = wqs + C * WPAD;
    float* wvs = wks + C * WPAD;
    float* xns = wvs + C * WPAD;
    int t = threadIdx.x, b = blockIdx.y, i0 = blockIdx.x * 128;

    for (int idx = t; idx < C * C; idx += 512) {
        int oo = idx >> 6, cc = idx & 63;
        wqs[cc * WPAD + oo] = Wq[idx];
        wks[cc * WPAD + oo] = Wk[idx];
        wvs[cc * WPAD + oo] = Wv[idx];
    }
    const float* xb = x + (size_t)b * C * NPIX;
    for (int idx = t; idx < C * 32; idx += 512) {
        int c = idx >> 5, i4 = idx & 31;
        float4 v = *(const float4*)(xb + (size_t)c * NPIX + i0 + i4 * 4);
        int g = c >> 1;
        float mean = g_stats[(b * NGROUPS + g) * 2 + 0];
        float rstd = g_stats[(b * NGROUPS + g) * 2 + 1];
        float ga = gamma[c] * rstd;
        float be = beta[c] - mean * ga;
        v.x = v.x * ga + be; v.y = v.y * ga + be;
        v.z = v.z * ga + be; v.w = v.w * ga + be;
        *(float4*)(xns + c * XPAD + i4 * 4) = v;
    }
    __syncthreads();

    int tx = t & 15, ty = t >> 4;          // ty in [0,32): channel pair
    int oo = ty * 2, ii = tx * 8;
    float aq[2][8], ak[2][8], av[2][8];
    #pragma unroll
    for (int r = 0; r < 2; r++)
        #pragma unroll
        for (int s = 0; s < 8; s++) { aq[r][s] = 0.f; ak[r][s] = 0.f; av[r][s] = 0.f; }

    #pragma unroll 4
    for (int c = 0; c < C; c++) {
        float xf[8];
        *(float4*)(xf)     = *(const float4*)(xns + c * XPAD + ii);
        *(float4*)(xf + 4) = *(const float4*)(xns + c * XPAD + ii + 4);
        float2 wq2 = *(const float2*)(wqs + c * WPAD + oo);
        float2 wk2 = *(const float2*)(wks + c * WPAD + oo);
        float2 wv2 = *(const float2*)(wvs + c * WPAD + oo);
        #pragma unroll
        for (int s = 0; s < 8; s++) {
            aq[0][s] += wq2.x * xf[s];  aq[1][s] += wq2.y * xf[s];
            ak[0][s] += wk2.x * xf[s];  ak[1][s] += wk2.y * xf[s];
            av[0][s] += wv2.x * xf[s];  av[1][s] += wv2.y * xf[s];
        }
    }

    float bi0[3], bi1[3];
    bi0[0] = bq[oo]; bi1[0] = bq[oo + 1];
    bi0[1] = bk[oo]; bi1[1] = bk[oo + 1];
    bi0[2] = bv[oo]; bi1[2] = bv[oo + 1];

    // ---- staged, coalesced epilogue ----
    uint32_t* bufh = (uint32_t*)smf;            // [128][33] words
    uint32_t* bufl = bufh + 128 * 33;
    int cw = t & 31, pg = t >> 5;

    #pragma unroll
    for (int p = 0; p < 3; p++) {
        __syncthreads();
        #pragma unroll
        for (int s = 0; s < 8; s++) {
            float v0 = (p == 0 ? aq[0][s] : p == 1 ? ak[0][s] : av[0][s]) + bi0[p];
            float v1 = (p == 0 ? aq[1][s] : p == 1 ? ak[1][s] : av[1][s]) + bi1[p];
            if (p == 0) { v0 *= 0.125f; v1 *= 0.125f; }
            uint32_t h = pack_bf16x2(v0, v1);
            int pix = ii + s;
            bufh[pix * 33 + ty] = h;
            if (p != 0) {
                bufl[pix * 33 + ty] = pack_bf16x2(v0 - __uint_as_float(h << 16),
                                                  v1 - __uint_as_float(h & 0xffff0000u));
            }
        }
        __syncthreads();
        __nv_bfloat16* dh = (p == 0) ? g_qh : (p == 1) ? g_kh : g_vh;
        uint32_t* gh = (uint32_t*)(dh + ((size_t)b * NPIX + i0) * C);
        #pragma unroll
        for (int e = 0; e < 8; e++) {
            int pix = pg * 8 + e;
            gh[pix * 32 + cw] = bufh[pix * 33 + cw];
        }
        if (p != 0) {
            __nv_bfloat16* dl = (p == 1) ? g_kl : g_vl;
            uint32_t* gl = (uint32_t*)(dl + ((size_t)b * NPIX + i0) * C);
            #pragma unroll
            for (int e = 0; e < 8; e++) {
                int pix = pg * 8 + e;
                gl[pix * 32 + cw] = bufl[pix * 33 + cw];
            }
        }
    }
}

// ============================================================================
// K2: mma.sync bf16 flash attention + fused output projection/residual.
// 2-term S = qh*(kh+kl), 2-term PV = ph*(vh+vl). 256 MMAs/warp/block.
// Smem: QH@0 | KV buf0@32K buf1@96K = 160K.
// ============================================================================
#define SM_QH    0
#define SM_KV    32768
#define KVBUF    65536
#define KV_KH    0
#define KV_KL    16384
#define KV_VH    32768
#define KV_VL    49152
#define SM_ATTN  163840

__device__ __forceinline__ void prefetch_kv(uint32_t smb, int buf, int j0,
        const uint4* kh4, const uint4* kl4, const uint4* vh4, const uint4* vl4, int t) {
    uint32_t base = smb + SM_KV + buf * KVBUF;
    #pragma unroll
    for (int q = 0; q < 4; q++) {
        int idx = t + q * 256;
        int row = idx >> 3, c16 = idx & 7;
        uint32_t sw = SWZ((uint32_t)(row * 128 + c16 * 16));
        size_t off = (size_t)(j0 + row) * 8 + c16;
        CP_ASYNC(base + KV_KH + sw, kh4 + off);
        CP_ASYNC(base + KV_KL + sw, kl4 + off);
        CP_ASYNC(base + KV_VH + sw, vh4 + off);
        CP_ASYNC(base + KV_VL + sw, vl4 + off);
    }
}

__global__ void __launch_bounds__(256) attn_kernel(
        const float* __restrict__ x, const float* __restrict__ Wo,
        const float* __restrict__ bo, float* __restrict__ out) {
    char* sm = dynsm;
    uint32_t smb = smem_u32(sm);
    int t = threadIdx.x, lane = t & 31, warp = t >> 5;
    int b = blockIdx.y, i0 = blockIdx.x * 128;

    const uint4* qh4 = (const uint4*)(g_qh + (size_t)b * NPIX * C);
    const uint4* kh4 = (const uint4*)(g_kh + (size_t)b * NPIX * C);
    const uint4* kl4 = (const uint4*)(g_kl + (size_t)b * NPIX * C);
    const uint4* vh4 = (const uint4*)(g_vh + (size_t)b * NPIX * C);
    const uint4* vl4 = (const uint4*)(g_vl + (size_t)b * NPIX * C);

    for (int idx = t; idx < 1024; idx += 256) {
        int row = idx >> 3, c16 = idx & 7;
        uint32_t sw = SWZ((uint32_t)(row * 128 + c16 * 16));
        *(uint4*)(sm + SM_QH + sw) = qh4[(size_t)(i0 + row) * 8 + c16];
    }
    prefetch_kv(smb, 0, 0, kh4, kl4, vh4, vl4, t);
    CP_COMMIT;
    __syncthreads();

    int mm = lane >> 3, r8 = lane & 7;
    int qRowB  = (warp * 16 + (mm & 1) * 8 + r8) * 128;
    int qColB  = (mm >> 1) * 16;
    int kKeyOff = (mm >> 1) * 8 + r8;
    int kColB   = (mm & 1) * 16;
    int vKeyOff = (mm & 1) * 8 + r8;
    int vColB   = (mm >> 1) * 16;

    uint32_t qh[4][4];
    #pragma unroll
    for (int kc = 0; kc < 4; kc++)
        LDSM_X4(qh[kc], smb + SM_QH + SWZ((uint32_t)(qRowB + kc * 32 + qColB)));

    float O[8][4];
    #pragma unroll
    for (int ct = 0; ct < 8; ct++)
        #pragma unroll
        for (int e = 0; e < 4; e++) O[ct][e] = 0.f;
    float l0 = 0.f, l1 = 0.f;

    for (int jb = 0; jb < 32; jb++) {
        if (jb + 1 < 32) {
            prefetch_kv(smb, (jb + 1) & 1, (jb + 1) * 128, kh4, kl4, vh4, vl4, t);
            CP_COMMIT;
            CP_WAIT1;
        } else {
            CP_WAIT0;
        }
        __syncthreads();
        uint32_t kvb = smb + SM_KV + (jb & 1) * KVBUF;

        // ---- S = qh * (kh + kl) ----
        float Sv[16][4];
        #pragma unroll
        for (int nt = 0; nt < 16; nt++)
            #pragma unroll
            for (int e = 0; e < 4; e++) Sv[nt][e] = 0.f;

        #pragma unroll
        for (int kc = 0; kc < 4; kc++) {
            #pragma unroll
            for (int ntp = 0; ntp < 8; ntp++) {
                uint32_t rowb = (uint32_t)((ntp * 16 + kKeyOff) * 128 + kc * 32 + kColB);
                uint32_t bh[4], bl[4];
                LDSM_X4(bh, kvb + KV_KH + SWZ(rowb));
                MMA(Sv[2 * ntp],     qh[kc], bh[0], bh[1]);
                MMA(Sv[2 * ntp + 1], qh[kc], bh[2], bh[3]);
                LDSM_X4(bl, kvb + KV_KL + SWZ(rowb));
                MMA(Sv[2 * ntp],     qh[kc], bl[0], bl[1]);
                MMA(Sv[2 * ntp + 1], qh[kc], bl[2], bl[3]);
            }
        }

        // ---- exp + row sums ----
        float rs0 = 0.f, rs1 = 0.f;
        #pragma unroll
        for (int nt = 0; nt < 16; nt++) {
            Sv[nt][0] = __expf(Sv[nt][0]);
            Sv[nt][1] = __expf(Sv[nt][1]);
            Sv[nt][2] = __expf(Sv[nt][2]);
            Sv[nt][3] = __expf(Sv[nt][3]);
            rs0 += Sv[nt][0] + Sv[nt][1];
            rs1 += Sv[nt][2] + Sv[nt][3];
        }
        rs0 += __shfl_xor_sync(0xffffffffu, rs0, 1);
        rs0 += __shfl_xor_sync(0xffffffffu, rs0, 2);
        rs1 += __shfl_xor_sync(0xffffffffu, rs1, 1);
        rs1 += __shfl_xor_sync(0xffffffffu, rs1, 2);
        l0 += rs0; l1 += rs1;

        // ---- O += ph * (vh + vl) ----
        #pragma unroll
        for (int kk = 0; kk < 8; kk++) {
            uint32_t ph[4];
            #pragma unroll
            for (int h = 0; h < 2; h++) {
                ph[2 * h]     = pack_bf16x2(Sv[2 * kk + h][0], Sv[2 * kk + h][1]);
                ph[2 * h + 1] = pack_bf16x2(Sv[2 * kk + h][2], Sv[2 * kk + h][3]);
            }
            #pragma unroll
            for (int ctp = 0; ctp < 4; ctp++) {
                uint32_t rowb = (uint32_t)((kk * 16 + vKeyOff) * 128 + ctp * 32 + vColB);
                uint32_t bh[4], bl[4];
                LDSM_X4T(bh, kvb + KV_VH + SWZ(rowb));
                MMA(O[2 * ctp],     ph, bh[0], bh[1]);
                MMA(O[2 * ctp + 1], ph, bh[2], bh[3]);
                LDSM_X4T(bl, kvb + KV_VL + SWZ(rowb));
                MMA(O[2 * ctp],     ph, bl[0], bl[1]);
                MMA(O[2 * ctp + 1], ph, bl[2], bl[3]);
            }
        }
        __syncthreads();
    }

    // ---- fused epilogue: Wo^T to smem, O/l transpose, proj + residual ----
    float* ws = (float*)(sm + SM_QH);
    for (int idx = t; idx < C * C; idx += 256) {
        int oo = idx >> 6, cc = idx & 63;
        ws[cc * WPAD + oo] = Wo[idx];
    }
    float inv0 = 1.f / l0, inv1 = 1.f / l1;
    float* sO = (float*)(sm + SM_KV);
    int r = warp * 16 + (lane >> 2);
    #pragma unroll
    for (int ct = 0; ct < 8; ct++) {
        int ch = ct * 8 + (lane & 3) * 2;
        sO[ch * XPAD + r]           = O[ct][0] * inv0;
        sO[(ch + 1) * XPAD + r]     = O[ct][1] * inv0;
        sO[ch * XPAD + r + 8]       = O[ct][2] * inv1;
        sO[(ch + 1) * XPAD + r + 8] = O[ct][3] * inv1;
    }
    __syncthreads();

    int tx = t & 15, ty = t >> 4;
    int oo = ty * 4, ii = tx * 8;
    float acc[4][8];
    #pragma unroll
    for (int rr = 0; rr < 4; rr++)
        #pragma unroll
        for (int s = 0; s < 8; s++) acc[rr][s] = 0.f;

    #pragma unroll 4
    for (int c = 0; c < C; c++) {
        float xf[8], wf[4];
        *(float4*)(xf)     = *(const float4*)(sO + c * XPAD + ii);
        *(float4*)(xf + 4) = *(const float4*)(sO + c * XPAD + ii + 4);
        *(float4*)(wf)     = *(const float4*)(ws + c * WPAD + oo);
        #pragma unroll
        for (int rr = 0; rr < 4; rr++)
            #pragma unroll
            for (int s = 0; s < 8; s++) acc[rr][s] += wf[rr] * xf[s];
    }
    #pragma unroll
    for (int rr = 0; rr < 4; rr++) {
        int o = oo + rr;
        float bv = bo[o];
        size_t off = ((size_t)(b * C + o)) * NPIX + i0 + ii;
        float4 x0 = *(const float4*)(x + off);
        float4 x1 = *(const float4*)(x + off + 4);
        float tmp[8];
        tmp[0] = x0.x + acc[rr][0] + bv; tmp[1] = x0.y + acc[rr][1] + bv;
        tmp[2] = x0.z + acc[rr][2] + bv; tmp[3] = x0.w + acc[rr][3] + bv;
        tmp[4] = x1.x + acc[rr][4] + bv; tmp[5] = x1.y + acc[rr][5] + bv;
        tmp[6] = x1.z + acc[rr][6] + bv; tmp[7] = x1.w + acc[rr][7] + bv;
        *(float4*)(out + off)     = *(float4*)tmp;
        *(float4*)(out + off + 4) = *(float4*)(tmp + 4);
    }
}

// ============================================================================
extern "C" void kernel_launch(void* const* d_in, const int* in_sizes, int n_in,
                              void* d_out, int out_size) {
    const float* x     = (const float*)d_in[0];
    const float* Wq    = (const float*)d_in[1];
    const float* bq    = (const float*)d_in[2];
    const float* Wk    = (const float*)d_in[3];
    const float* bk    = (const float*)d_in[4];
    const float* Wv    = (const float*)d_in[5];
    const float* bv    = (const float*)d_in[6];
    const float* Wo    = (const float*)d_in[7];
    const float* bo    = (const float*)d_in[8];
    const float* gamma = (const float*)d_in[9];
    const float* beta  = (const float*)d_in[10];
    float* out = (float*)d_out;

    const int QKV_SMEM = (3 * C * WPAD + C * XPAD) * 4;

    cudaFuncSetAttribute(qkv_kernel,  cudaFuncAttributeMaxDynamicSharedMemorySize, QKV_SMEM);
    cudaFuncSetAttribute(attn_kernel, cudaFuncAttributeMaxDynamicSharedMemorySize, SM_ATTN);

    gn_stats_kernel<<<dim3(NGROUPS, BATCH), 512>>>(x);
    qkv_kernel<<<dim3(NPIX / 128, BATCH), 512, QKV_SMEM>>>(x, Wq, bq, Wk, bk, Wv, bv, gamma, beta);
    attn_kernel<<<dim3(NPIX / 128, BATCH), 256, SM_ATTN>>>(x, Wo, bo, out);
}

// round 10
// speedup vs baseline: 2.5629x; 1.2926x over previous
#include <cuda_runtime.h>
#include <cuda_bf16.h>
#include <cstdint>
#include <cstddef>

#define BATCH   4
#define C       64
#define NPIX    4096
#define NGROUPS 32
#define WPAD    68
#define XPAD    132

// ---------------- scratch (device globals; no runtime allocation) ------------
__device__ __nv_bfloat16 g_qh[BATCH * NPIX * C];   // [b][n][c] rows of 128B
__device__ __nv_bfloat16 g_kh[BATCH * NPIX * C];
__device__ __nv_bfloat16 g_vh[BATCH * NPIX * C];
__device__ float         g_stats[BATCH * NGROUPS * 2];

extern __shared__ char dynsm[];

// ---------------- helpers ----------------------------------------------------
__device__ __forceinline__ uint32_t smem_u32(const void* p) {
    uint32_t a;
    asm("{ .reg .u64 t; cvta.to.shared.u64 t, %1; cvt.u32.u64 %0, t; }" : "=r"(a) : "l"(p));
    return a;
}
#define SWZ(o) ((o) ^ (((o) >> 3) & 0x70))

#define CP_ASYNC(dst, src) \
    asm volatile("cp.async.cg.shared.global [%0], [%1], 16;" :: "r"(dst), "l"(src) : "memory")
#define CP_COMMIT asm volatile("cp.async.commit_group;" ::: "memory")
#define CP_WAIT1  asm volatile("cp.async.wait_group 1;" ::: "memory")
#define CP_WAIT0  asm volatile("cp.async.wait_group 0;" ::: "memory")

#define LDSM_X4(r, a) \
    asm volatile("ldmatrix.sync.aligned.m8n8.x4.shared.b16 {%0,%1,%2,%3}, [%4];" \
        : "=r"((r)[0]), "=r"((r)[1]), "=r"((r)[2]), "=r"((r)[3]) : "r"(a))
#define LDSM_X4T(r, a) \
    asm volatile("ldmatrix.sync.aligned.m8n8.x4.trans.shared.b16 {%0,%1,%2,%3}, [%4];" \
        : "=r"((r)[0]), "=r"((r)[1]), "=r"((r)[2]), "=r"((r)[3]) : "r"(a))

// D += A * B  (m16n8k16, bf16 in, f32 accum)
#define MMA(c, a, b0, b1) \
    asm volatile("mma.sync.aligned.m16n8k16.row.col.f32.bf16.bf16.f32 " \
        "{%0,%1,%2,%3}, {%4,%5,%6,%7}, {%8,%9}, {%0,%1,%2,%3};" \
        : "+f"((c)[0]), "+f"((c)[1]), "+f"((c)[2]), "+f"((c)[3]) \
        : "r"((a)[0]), "r"((a)[1]), "r"((a)[2]), "r"((a)[3]), "r"(b0), "r"(b1))

__device__ __forceinline__ uint32_t pack_bf16x2(float lo, float hi) {
    uint32_t r;
    asm("cvt.rn.bf16x2.f32 %0, %1, %2;" : "=r"(r) : "f"(hi), "f"(lo));
    return r;
}

// ============================================================================
// K0: GroupNorm statistics (512 threads)
// ============================================================================
__global__ void __launch_bounds__(512) gn_stats_kernel(const float* __restrict__ x) {
    int g = blockIdx.x, b = blockIdx.y;
    const float* base = x + ((size_t)b * C + (size_t)g * 2) * NPIX;
    float s = 0.f, s2 = 0.f;
    const float4* p4 = (const float4*)base;
    for (int idx = threadIdx.x; idx < (2 * NPIX) / 4; idx += blockDim.x) {
        float4 v = p4[idx];
        s  += v.x + v.y + v.z + v.w;
        s2 += v.x * v.x + v.y * v.y + v.z * v.z + v.w * v.w;
    }
    __shared__ float rs[32], rs2[32];
    #pragma unroll
    for (int o = 16; o; o >>= 1) {
        s  += __shfl_xor_sync(0xffffffffu, s,  o);
        s2 += __shfl_xor_sync(0xffffffffu, s2, o);
    }
    int lane = threadIdx.x & 31, w = threadIdx.x >> 5;
    if (lane == 0) { rs[w] = s; rs2[w] = s2; }
    __syncthreads();
    if (w == 0) {
        s  = (lane < (int)(blockDim.x >> 5)) ? rs[lane]  : 0.f;
        s2 = (lane < (int)(blockDim.x >> 5)) ? rs2[lane] : 0.f;
        #pragma unroll
        for (int o = 16; o; o >>= 1) {
            s  += __shfl_xor_sync(0xffffffffu, s,  o);
            s2 += __shfl_xor_sync(0xffffffffu, s2, o);
        }
        if (lane == 0) {
            const float invn = 1.f / (2.f * NPIX);
            float mean = s * invn;
            float var  = s2 * invn - mean * mean;
            g_stats[(b * NGROUPS + g) * 2 + 0] = mean;
            g_stats[(b * NGROUPS + g) * 2 + 1] = rsqrtf(var + 1e-5f);
        }
    }
}

// ============================================================================
// K1: GroupNorm-apply + QKV projection (512 threads, staged coalesced stores).
// All of q, k, v emit plain bf16 (pure-bf16 attention path).
// q pre-scaled by 1/sqrt(C) = 0.125.
// ============================================================================
__global__ void __launch_bounds__(512) qkv_kernel(
                           const float* __restrict__ x,
                           const float* __restrict__ Wq, const float* __restrict__ bq,
                           const float* __restrict__ Wk, const float* __restrict__ bk,
                           const float* __restrict__ Wv, const float* __restrict__ bv,
                           const float* __restrict__ gamma, const float* __restrict__ beta) {
    float* smf = (float*)dynsm;
    float* wqs = smf;
    float* wks = wqs + C * WPAD;
    float* wvs = wks + C * WPAD;
    float* xns = wvs + C * WPAD;
    int t = threadIdx.x, b = blockIdx.y, i0 = blockIdx.x * 128;

    for (int idx = t; idx < C * C; idx += 512) {
        int oo = idx >> 6, cc = idx & 63;
        wqs[cc * WPAD + oo] = Wq[idx];
        wks[cc * WPAD + oo] = Wk[idx];
        wvs[cc * WPAD + oo] = Wv[idx];
    }
    const float* xb = x + (size_t)b * C * NPIX;
    for (int idx = t; idx < C * 32; idx += 512) {
        int c = idx >> 5, i4 = idx & 31;
        float4 v = *(const float4*)(xb + (size_t)c * NPIX + i0 + i4 * 4);
        int g = c >> 1;
        float mean = g_stats[(b * NGROUPS + g) * 2 + 0];
        float rstd = g_stats[(b * NGROUPS + g) * 2 + 1];
        float ga = gamma[c] * rstd;
        float be = beta[c] - mean * ga;
        v.x = v.x * ga + be; v.y = v.y * ga + be;
        v.z = v.z * ga + be; v.w = v.w * ga + be;
        *(float4*)(xns + c * XPAD + i4 * 4) = v;
    }
    __syncthreads();

    int tx = t & 15, ty = t >> 4;          // ty in [0,32): channel pair
    int oo = ty * 2, ii = tx * 8;
    float aq[2][8], ak[2][8], av[2][8];
    #pragma unroll
    for (int r = 0; r < 2; r++)
        #pragma unroll
        for (int s = 0; s < 8; s++) { aq[r][s] = 0.f; ak[r][s] = 0.f; av[r][s] = 0.f; }

    #pragma unroll 4
    for (int c = 0; c < C; c++) {
        float xf[8];
        *(float4*)(xf)     = *(const float4*)(xns + c * XPAD + ii);
        *(float4*)(xf + 4) = *(const float4*)(xns + c * XPAD + ii + 4);
        float2 wq2 = *(const float2*)(wqs + c * WPAD + oo);
        float2 wk2 = *(const float2*)(wks + c * WPAD + oo);
        float2 wv2 = *(const float2*)(wvs + c * WPAD + oo);
        #pragma unroll
        for (int s = 0; s < 8; s++) {
            aq[0][s] += wq2.x * xf[s];  aq[1][s] += wq2.y * xf[s];
            ak[0][s] += wk2.x * xf[s];  ak[1][s] += wk2.y * xf[s];
            av[0][s] += wv2.x * xf[s];  av[1][s] += wv2.y * xf[s];
        }
    }

    float bi0[3], bi1[3];
    bi0[0] = bq[oo]; bi1[0] = bq[oo + 1];
    bi0[1] = bk[oo]; bi1[1] = bk[oo + 1];
    bi0[2] = bv[oo]; bi1[2] = bv[oo + 1];

    // ---- staged, coalesced epilogue (hi only) ----
    uint32_t* bufh = (uint32_t*)smf;            // [128][33] words
    int cw = t & 31, pg = t >> 5;

    #pragma unroll
    for (int p = 0; p < 3; p++) {
        __syncthreads();
        #pragma unroll
        for (int s = 0; s < 8; s++) {
            float v0 = (p == 0 ? aq[0][s] : p == 1 ? ak[0][s] : av[0][s]) + bi0[p];
            float v1 = (p == 0 ? aq[1][s] : p == 1 ? ak[1][s] : av[1][s]) + bi1[p];
            if (p == 0) { v0 *= 0.125f; v1 *= 0.125f; }
            bufh[(ii + s) * 33 + ty] = pack_bf16x2(v0, v1);
        }
        __syncthreads();
        __nv_bfloat16* dh = (p == 0) ? g_qh : (p == 1) ? g_kh : g_vh;
        uint32_t* gh = (uint32_t*)(dh + ((size_t)b * NPIX + i0) * C);
        #pragma unroll
        for (int e = 0; e < 8; e++) {
            int pix = pg * 8 + e;
            gh[pix * 32 + cw] = bufh[pix * 33 + cw];
        }
    }
}

// ============================================================================
// K2: pure-bf16 mma.sync flash attention + fused output projection/residual.
// 1-term S = qh*kh, 1-term PV = ph*vh. 128 MMAs/warp/block.
// Smem: QH@0 (16K) | KV buf0@16K buf1@48K (each: KH 16K + VH 16K) = 80K.
// Epilogue reuse: ws@0 (17408B), sO@20480 (33792B).
// ============================================================================
#define SM_QH    0
#define SM_KV    16384
#define KVBUF    32768
#define KV_KH    0
#define KV_VH    16384
#define SM_ATTN  81920

__device__ __forceinline__ void prefetch_kv(uint32_t smb, int buf, int j0,
        const uint4* kh4, const uint4* vh4, int t) {
    uint32_t base = smb + SM_KV + buf * KVBUF;
    #pragma unroll
    for (int q = 0; q < 4; q++) {
        int idx = t + q * 256;
        int row = idx >> 3, c16 = idx & 7;
        uint32_t sw = SWZ((uint32_t)(row * 128 + c16 * 16));
        size_t off = (size_t)(j0 + row) * 8 + c16;
        CP_ASYNC(base + KV_KH + sw, kh4 + off);
        CP_ASYNC(base + KV_VH + sw, vh4 + off);
    }
}

__global__ void __launch_bounds__(256) attn_kernel(
        const float* __restrict__ x, const float* __restrict__ Wo,
        const float* __restrict__ bo, float* __restrict__ out) {
    char* sm = dynsm;
    uint32_t smb = smem_u32(sm);
    int t = threadIdx.x, lane = t & 31, warp = t >> 5;
    int b = blockIdx.y, i0 = blockIdx.x * 128;

    const uint4* qh4 = (const uint4*)(g_qh + (size_t)b * NPIX * C);
    const uint4* kh4 = (const uint4*)(g_kh + (size_t)b * NPIX * C);
    const uint4* vh4 = (const uint4*)(g_vh + (size_t)b * NPIX * C);

    for (int idx = t; idx < 1024; idx += 256) {
        int row = idx >> 3, c16 = idx & 7;
        uint32_t sw = SWZ((uint32_t)(row * 128 + c16 * 16));
        *(uint4*)(sm + SM_QH + sw) = qh4[(size_t)(i0 + row) * 8 + c16];
    }
    prefetch_kv(smb, 0, 0, kh4, vh4, t);
    CP_COMMIT;
    __syncthreads();

    int mm = lane >> 3, r8 = lane & 7;
    int qRowB  = (warp * 16 + (mm & 1) * 8 + r8) * 128;
    int qColB  = (mm >> 1) * 16;
    int kKeyOff = (mm >> 1) * 8 + r8;
    int kColB   = (mm & 1) * 16;
    int vKeyOff = (mm & 1) * 8 + r8;
    int vColB   = (mm >> 1) * 16;

    uint32_t qh[4][4];
    #pragma unroll
    for (int kc = 0; kc < 4; kc++)
        LDSM_X4(qh[kc], smb + SM_QH + SWZ((uint32_t)(qRowB + kc * 32 + qColB)));

    float O[8][4];
    #pragma unroll
    for (int ct = 0; ct < 8; ct++)
        #pragma unroll
        for (int e = 0; e < 4; e++) O[ct][e] = 0.f;
    float l0 = 0.f, l1 = 0.f;

    for (int jb = 0; jb < 32; jb++) {
        if (jb + 1 < 32) {
            prefetch_kv(smb, (jb + 1) & 1, (jb + 1) * 128, kh4, vh4, t);
            CP_COMMIT;
            CP_WAIT1;
        } else {
            CP_WAIT0;
        }
        __syncthreads();
        uint32_t kvb = smb + SM_KV + (jb & 1) * KVBUF;

        // ---- S = qh * kh ----
        float Sv[16][4];
        #pragma unroll
        for (int nt = 0; nt < 16; nt++)
            #pragma unroll
            for (int e = 0; e < 4; e++) Sv[nt][e] = 0.f;

        #pragma unroll
        for (int kc = 0; kc < 4; kc++) {
            #pragma unroll
            for (int ntp = 0; ntp < 8; ntp++) {
                uint32_t rowb = (uint32_t)((ntp * 16 + kKeyOff) * 128 + kc * 32 + kColB);
                uint32_t bh[4];
                LDSM_X4(bh, kvb + KV_KH + SWZ(rowb));
                MMA(Sv[2 * ntp],     qh[kc], bh[0], bh[1]);
                MMA(Sv[2 * ntp + 1], qh[kc], bh[2], bh[3]);
            }
        }

        // ---- exp + row sums ----
        float rs0 = 0.f, rs1 = 0.f;
        #pragma unroll
        for (int nt = 0; nt < 16; nt++) {
            Sv[nt][0] = __expf(Sv[nt][0]);
            Sv[nt][1] = __expf(Sv[nt][1]);
            Sv[nt][2] = __expf(Sv[nt][2]);
            Sv[nt][3] = __expf(Sv[nt][3]);
            rs0 += Sv[nt][0] + Sv[nt][1];
            rs1 += Sv[nt][2] + Sv[nt][3];
        }
        rs0 += __shfl_xor_sync(0xffffffffu, rs0, 1);
        rs0 += __shfl_xor_sync(0xffffffffu, rs0, 2);
        rs1 += __shfl_xor_sync(0xffffffffu, rs1, 1);
        rs1 += __shfl_xor_sync(0xffffffffu, rs1, 2);
        l0 += rs0; l1 += rs1;

        // ---- O += ph * vh ----
        #pragma unroll
        for (int kk = 0; kk < 8; kk++) {
            uint32_t ph[4];
            #pragma unroll
            for (int h = 0; h < 2; h++) {
                ph[2 * h]     = pack_bf16x2(Sv[2 * kk + h][0], Sv[2 * kk + h][1]);
                ph[2 * h + 1] = pack_bf16x2(Sv[2 * kk + h][2], Sv[2 * kk + h][3]);
            }
            #pragma unroll
            for (int ctp = 0; ctp < 4; ctp++) {
                uint32_t rowb = (uint32_t)((kk * 16 + vKeyOff) * 128 + ctp * 32 + vColB);
                uint32_t bh[4];
                LDSM_X4T(bh, kvb + KV_VH + SWZ(rowb));
                MMA(O[2 * ctp],     ph, bh[0], bh[1]);
                MMA(O[2 * ctp + 1], ph, bh[2], bh[3]);
            }
        }
        __syncthreads();
    }

    // ---- fused epilogue: Wo^T to smem, O/l transpose, proj + residual ----
    float* ws = (float*)(sm + 0);              // 17408 B
    for (int idx = t; idx < C * C; idx += 256) {
        int oo = idx >> 6, cc = idx & 63;
        ws[cc * WPAD + oo] = Wo[idx];
    }
    float inv0 = 1.f / l0, inv1 = 1.f / l1;
    float* sO = (float*)(sm + 20480);          // [64][XPAD] f32 = 33792 B, ends 54272
    int r = warp * 16 + (lane >> 2);
    #pragma unroll
    for (int ct = 0; ct < 8; ct++) {
        int ch = ct * 8 + (lane & 3) * 2;
        sO[ch * XPAD + r]           = O[ct][0] * inv0;
        sO[(ch + 1) * XPAD + r]     = O[ct][1] * inv0;
        sO[ch * XPAD + r + 8]       = O[ct][2] * inv1;
        sO[(ch + 1) * XPAD + r + 8] = O[ct][3] * inv1;
    }
    __syncthreads();

    int tx = t & 15, ty = t >> 4;
    int oo = ty * 4, ii = tx * 8;
    float acc[4][8];
    #pragma unroll
    for (int rr = 0; rr < 4; rr++)
        #pragma unroll
        for (int s = 0; s < 8; s++) acc[rr][s] = 0.f;

    #pragma unroll 4
    for (int c = 0; c < C; c++) {
        float xf[8], wf[4];
        *(float4*)(xf)     = *(const float4*)(sO + c * XPAD + ii);
        *(float4*)(xf + 4) = *(const float4*)(sO + c * XPAD + ii + 4);
        *(float4*)(wf)     = *(const float4*)(ws + c * WPAD + oo);
        #pragma unroll
        for (int rr = 0; rr < 4; rr++)
            #pragma unroll
            for (int s = 0; s < 8; s++) acc[rr][s] += wf[rr] * xf[s];
    }
    #pragma unroll
    for (int rr = 0; rr < 4; rr++) {
        int o = oo + rr;
        float bv = bo[o];
        size_t off = ((size_t)(b * C + o)) * NPIX + i0 + ii;
        float4 x0 = *(const float4*)(x + off);
        float4 x1 = *(const float4*)(x + off + 4);
        float tmp[8];
        tmp[0] = x0.x + acc[rr][0] + bv; tmp[1] = x0.y + acc[rr][1] + bv;
        tmp[2] = x0.z + acc[rr][2] + bv; tmp[3] = x0.w + acc[rr][3] + bv;
        tmp[4] = x1.x + acc[rr][4] + bv; tmp[5] = x1.y + acc[rr][5] + bv;
        tmp[6] = x1.z + acc[rr][6] + bv; tmp[7] = x1.w + acc[rr][7] + bv;
        *(float4*)(out + off)     = *(float4*)tmp;
        *(float4*)(out + off + 4) = *(float4*)(tmp + 4);
    }
}

// ============================================================================
extern "C" void kernel_launch(void* const* d_in, const int* in_sizes, int n_in,
                              void* d_out, int out_size) {
    const float* x     = (const float*)d_in[0];
    const float* Wq    = (const float*)d_in[1];
    const float* bq    = (const float*)d_in[2];
    const float* Wk    = (const float*)d_in[3];
    const float* bk    = (const float*)d_in[4];
    const float* Wv    = (const float*)d_in[5];
    const float* bv    = (const float*)d_in[6];
    const float* Wo    = (const float*)d_in[7];
    const float* bo    = (const float*)d_in[8];
    const float* gamma = (const float*)d_in[9];
    const float* beta  = (const float*)d_in[10];
    float* out = (float*)d_out;

    const int QKV_SMEM = (3 * C * WPAD + C * XPAD) * 4;

    cudaFuncSetAttribute(qkv_kernel,  cudaFuncAttributeMaxDynamicSharedMemorySize, QKV_SMEM);
    cudaFuncSetAttribute(attn_kernel, cudaFuncAttributeMaxDynamicSharedMemorySize, SM_ATTN);

    gn_stats_kernel<<<dim3(NGROUPS, BATCH), 512>>>(x);
    qkv_kernel<<<dim3(NPIX / 128, BATCH), 512, QKV_SMEM>>>(x, Wq, bq, Wk, bk, Wv, bv, gamma, beta);
    attn_kernel<<<dim3(NPIX / 128, BATCH), 256, SM_ATTN>>>(x, Wo, bo, out);
}

// round 11
// speedup vs baseline: 2.6842x; 1.0473x over previous
#include <cuda_runtime.h>
#include <cuda_bf16.h>
#include <cstdint>
#include <cstddef>

#define BATCH   4
#define C       64
#define NPIX    4096
#define NGROUPS 32
#define WPAD    68
#define XPAD    132

// ---------------- scratch (device globals; no runtime allocation) ------------
__device__ __nv_bfloat16 g_qh[BATCH * NPIX * C];   // [b][n][c] rows of 128B
__device__ __nv_bfloat16 g_kh[BATCH * NPIX * C];
__device__ __nv_bfloat16 g_vh[BATCH * NPIX * C];
__device__ float         g_stats[BATCH * NGROUPS * 2];

extern __shared__ char dynsm[];

// ---------------- helpers ----------------------------------------------------
__device__ __forceinline__ uint32_t smem_u32(const void* p) {
    uint32_t a;
    asm("{ .reg .u64 t; cvta.to.shared.u64 t, %1; cvt.u32.u64 %0, t; }" : "=r"(a) : "l"(p));
    return a;
}
#define SWZ(o) ((o) ^ (((o) >> 3) & 0x70))

#define CP_ASYNC(dst, src) \
    asm volatile("cp.async.cg.shared.global [%0], [%1], 16;" :: "r"(dst), "l"(src) : "memory")
#define CP_COMMIT asm volatile("cp.async.commit_group;" ::: "memory")
#define CP_WAIT1  asm volatile("cp.async.wait_group 1;" ::: "memory")
#define CP_WAIT0  asm volatile("cp.async.wait_group 0;" ::: "memory")

#define LDSM_X4(r, a) \
    asm volatile("ldmatrix.sync.aligned.m8n8.x4.shared.b16 {%0,%1,%2,%3}, [%4];" \
        : "=r"((r)[0]), "=r"((r)[1]), "=r"((r)[2]), "=r"((r)[3]) : "r"(a))
#define LDSM_X4T(r, a) \
    asm volatile("ldmatrix.sync.aligned.m8n8.x4.trans.shared.b16 {%0,%1,%2,%3}, [%4];" \
        : "=r"((r)[0]), "=r"((r)[1]), "=r"((r)[2]), "=r"((r)[3]) : "r"(a))

// D += A * B  (m16n8k16, bf16 in, f32 accum)
#define MMA(c, a, b0, b1) \
    asm volatile("mma.sync.aligned.m16n8k16.row.col.f32.bf16.bf16.f32 " \
        "{%0,%1,%2,%3}, {%4,%5,%6,%7}, {%8,%9}, {%0,%1,%2,%3};" \
        : "+f"((c)[0]), "+f"((c)[1]), "+f"((c)[2]), "+f"((c)[3]) \
        : "r"((a)[0]), "r"((a)[1]), "r"((a)[2]), "r"((a)[3]), "r"(b0), "r"(b1))

__device__ __forceinline__ uint32_t pack_bf16x2(float lo, float hi) {
    uint32_t r;
    asm("cvt.rn.bf16x2.f32 %0, %1, %2;" : "=r"(r) : "f"(hi), "f"(lo));
    return r;
}

// ============================================================================
// K0: GroupNorm statistics (512 threads) — unchanged
// ============================================================================
__global__ void __launch_bounds__(512) gn_stats_kernel(const float* __restrict__ x) {
    int g = blockIdx.x, b = blockIdx.y;
    const float* base = x + ((size_t)b * C + (size_t)g * 2) * NPIX;
    float s = 0.f, s2 = 0.f;
    const float4* p4 = (const float4*)base;
    for (int idx = threadIdx.x; idx < (2 * NPIX) / 4; idx += blockDim.x) {
        float4 v = p4[idx];
        s  += v.x + v.y + v.z + v.w;
        s2 += v.x * v.x + v.y * v.y + v.z * v.z + v.w * v.w;
    }
    __shared__ float rs[32], rs2[32];
    #pragma unroll
    for (int o = 16; o; o >>= 1) {
        s  += __shfl_xor_sync(0xffffffffu, s,  o);
        s2 += __shfl_xor_sync(0xffffffffu, s2, o);
    }
    int lane = threadIdx.x & 31, w = threadIdx.x >> 5;
    if (lane == 0) { rs[w] = s; rs2[w] = s2; }
    __syncthreads();
    if (w == 0) {
        s  = (lane < (int)(blockDim.x >> 5)) ? rs[lane]  : 0.f;
        s2 = (lane < (int)(blockDim.x >> 5)) ? rs2[lane] : 0.f;
        #pragma unroll
        for (int o = 16; o; o >>= 1) {
            s  += __shfl_xor_sync(0xffffffffu, s,  o);
            s2 += __shfl_xor_sync(0xffffffffu, s2, o);
        }
        if (lane == 0) {
            const float invn = 1.f / (2.f * NPIX);
            float mean = s * invn;
            float var  = s2 * invn - mean * mean;
            g_stats[(b * NGROUPS + g) * 2 + 0] = mean;
            g_stats[(b * NGROUPS + g) * 2 + 1] = rsqrtf(var + 1e-5f);
        }
    }
}

// ============================================================================
// K1: HMMA QKV, take 2.  D^T[o][pix] = W[o][c] * xn[c][pix]  (3-term split:
// wh*xh + wl*xh + wh*xl -> fp32-accurate).  No input transposes:
//   A = W rows (attn-Q LDSM_X4 pattern), staged hi/lo with 8B vector stores.
//   B = xn [c][pix] rows (attn-V LDSM_X4T pattern), staged straight from
//       channel-major x with 8B vector stores.
// 384 threads = 12 warps: warp/4 = projection (Q,K,V), warp%4 = m16 o-tile.
// Output: accums (+bias, q*0.125) -> f32 smem stage -> coalesced [pix][c]
// packed bf16x2 stores (R7-proven path), 3 rounds (one per projection).
// Smem: WH 3x8K@0  WL 3x8K@24576  XH 2x8K@49152  XL 2x8K@65536
//       sO f32[64][132]@81920  -> total 115712 B
// ============================================================================
#define QW_H     0
#define QW_L     24576
#define QX_H     49152
#define QX_L     65536
#define Q_SO     81920
#define QKV_SMEM 115712

__global__ void __launch_bounds__(384) qkv_kernel(
        const float* __restrict__ x,
        const float* __restrict__ Wq, const float* __restrict__ bq,
        const float* __restrict__ Wk, const float* __restrict__ bk,
        const float* __restrict__ Wv, const float* __restrict__ bv,
        const float* __restrict__ gamma, const float* __restrict__ beta) {
    char* sm = dynsm;
    uint32_t smb = smem_u32(sm);
    int t = threadIdx.x, lane = t & 31, warp = t >> 5;
    int b = blockIdx.y, i0 = blockIdx.x * 128;

    // ---- stage W hi/lo: [o][c] rows of 128B, SW128, 8B vector stores ----
    const float* Ws[3] = { Wq, Wk, Wv };
    for (int idx = t; idx < 3 * 1024; idx += 384) {
        int p = idx >> 10, rem = idx & 1023;
        int o = rem >> 4, c4 = (rem & 15) * 4;
        float4 w = *(const float4*)(Ws[p] + o * C + c4);
        uint32_t h01 = pack_bf16x2(w.x, w.y);
        uint32_t h23 = pack_bf16x2(w.z, w.w);
        uint32_t sw = SWZ((uint32_t)(o * 128 + c4 * 2));
        *(uint2*)(sm + QW_H + p * 8192 + sw) = make_uint2(h01, h23);
        uint32_t l01 = pack_bf16x2(w.x - __uint_as_float(h01 << 16),
                                   w.y - __uint_as_float(h01 & 0xffff0000u));
        uint32_t l23 = pack_bf16x2(w.z - __uint_as_float(h23 << 16),
                                   w.w - __uint_as_float(h23 & 0xffff0000u));
        *(uint2*)(sm + QW_L + p * 8192 + sw) = make_uint2(l01, l23);
    }
    // ---- stage xn hi/lo: [c][pix] rows (two 64-pix halves of 128B rows) ----
    const float* xb = x + (size_t)b * C * NPIX;
    for (int idx = t; idx < C * 32; idx += 384) {
        int c = idx >> 5, pix = (idx & 31) * 4;
        float4 v = *(const float4*)(xb + (size_t)c * NPIX + i0 + pix);
        int g = c >> 1;
        float mean = g_stats[(b * NGROUPS + g) * 2 + 0];
        float rstd = g_stats[(b * NGROUPS + g) * 2 + 1];
        float ga = gamma[c] * rstd, be = beta[c] - mean * ga;
        v.x = v.x * ga + be; v.y = v.y * ga + be;
        v.z = v.z * ga + be; v.w = v.w * ga + be;
        uint32_t h01 = pack_bf16x2(v.x, v.y);
        uint32_t h23 = pack_bf16x2(v.z, v.w);
        int half = (pix >= 64) ? 8192 : 0;
        uint32_t sw = SWZ((uint32_t)(c * 128 + (pix & 63) * 2));
        *(uint2*)(sm + QX_H + half + sw) = make_uint2(h01, h23);
        uint32_t l01 = pack_bf16x2(v.x - __uint_as_float(h01 << 16),
                                   v.y - __uint_as_float(h01 & 0xffff0000u));
        uint32_t l23 = pack_bf16x2(v.z - __uint_as_float(h23 << 16),
                                   v.w - __uint_as_float(h23 & 0xffff0000u));
        *(uint2*)(sm + QX_L + half + sw) = make_uint2(l01, l23);
    }
    __syncthreads();

    int proj = warp >> 2, warpM = warp & 3;
    int mm = lane >> 3, r8 = lane & 7;
    // A-frag geometry (attn-Q pattern)
    int aRowB = (warpM * 16 + (mm & 1) * 8 + r8) * 128;
    int aColB = (mm >> 1) * 16;
    // B-frag geometry (attn-V trans pattern): storage rows = c (k), cols = pix (n)
    int xKOff = (mm & 1) * 8 + r8;
    int xColB = (mm >> 1) * 16;

    uint32_t ah[4][4], al[4][4];
    #pragma unroll
    for (int kc = 0; kc < 4; kc++) {
        uint32_t sw = SWZ((uint32_t)(aRowB + kc * 32 + aColB));
        LDSM_X4(ah[kc], smb + QW_H + proj * 8192 + sw);
        LDSM_X4(al[kc], smb + QW_L + proj * 8192 + sw);
    }

    float acc[16][4];
    #pragma unroll
    for (int nt = 0; nt < 16; nt++)
        #pragma unroll
        for (int e = 0; e < 4; e++) acc[nt][e] = 0.f;

    #pragma unroll
    for (int npp = 0; npp < 8; npp++) {          // n16 tiles (pix)
        uint32_t xh_base = smb + QX_H + (npp >> 2) * 8192;
        uint32_t xl_base = smb + QX_L + (npp >> 2) * 8192;
        int np16 = npp & 3;
        #pragma unroll
        for (int kc = 0; kc < 4; kc++) {
            uint32_t rowb = (uint32_t)((kc * 16 + xKOff) * 128 + np16 * 32 + xColB);
            uint32_t bh[4], bl[4];
            LDSM_X4T(bh, xh_base + SWZ(rowb));
            MMA(acc[2 * npp],     ah[kc], bh[0], bh[1]);
            MMA(acc[2 * npp + 1], ah[kc], bh[2], bh[3]);
            MMA(acc[2 * npp],     al[kc], bh[0], bh[1]);
            MMA(acc[2 * npp + 1], al[kc], bh[2], bh[3]);
            LDSM_X4T(bl, xl_base + SWZ(rowb));
            MMA(acc[2 * npp],     ah[kc], bl[0], bl[1]);
            MMA(acc[2 * npp + 1], ah[kc], bl[2], bl[3]);
        }
    }

    // bias + scale for this warp's o rows
    const float* biasA = (proj == 0) ? bq : (proj == 1) ? bk : bv;
    float scale = (proj == 0) ? 0.125f : 1.0f;
    int o0 = warpM * 16 + (lane >> 2);
    int o1 = o0 + 8;
    float b0 = biasA[o0], b1 = biasA[o1];

    float* sO = (float*)(sm + Q_SO);             // [64][XPAD] f32
    int cw = t & 31, pg = t >> 5;

    #pragma unroll
    for (int rp = 0; rp < 3; rp++) {
        __syncthreads();                         // sO free
        if (proj == rp) {
            #pragma unroll
            for (int nt = 0; nt < 16; nt++) {
                int pix = nt * 8 + (lane & 3) * 2;
                *(float2*)(sO + o0 * XPAD + pix) =
                    make_float2((acc[nt][0] + b0) * scale, (acc[nt][1] + b0) * scale);
                *(float2*)(sO + o1 * XPAD + pix) =
                    make_float2((acc[nt][2] + b1) * scale, (acc[nt][3] + b1) * scale);
            }
        }
        __syncthreads();
        __nv_bfloat16* dh = (rp == 0) ? g_qh : (rp == 1) ? g_kh : g_vh;
        uint32_t* gh = (uint32_t*)(dh + ((size_t)b * NPIX + i0) * C);
        for (int pix = pg; pix < 128; pix += 12) {
            float f0 = sO[(2 * cw) * XPAD + pix];
            float f1 = sO[(2 * cw + 1) * XPAD + pix];
            gh[pix * 32 + cw] = pack_bf16x2(f0, f1);
        }
    }
}

// ============================================================================
// K2: pure-bf16 mma.sync flash attention + fused output projection/residual.
// (unchanged from R10)
// ============================================================================
#define SM_QH    0
#define SM_KV    16384
#define KVBUF    32768
#define KV_KH    0
#define KV_VH    16384
#define SM_ATTN  81920

__device__ __forceinline__ void prefetch_kv(uint32_t smb, int buf, int j0,
        const uint4* kh4, const uint4* vh4, int t) {
    uint32_t base = smb + SM_KV + buf * KVBUF;
    #pragma unroll
    for (int q = 0; q < 4; q++) {
        int idx = t + q * 256;
        int row = idx >> 3, c16 = idx & 7;
        uint32_t sw = SWZ((uint32_t)(row * 128 + c16 * 16));
        size_t off = (size_t)(j0 + row) * 8 + c16;
        CP_ASYNC(base + KV_KH + sw, kh4 + off);
        CP_ASYNC(base + KV_VH + sw, vh4 + off);
    }
}

__global__ void __launch_bounds__(256) attn_kernel(
        const float* __restrict__ x, const float* __restrict__ Wo,
        const float* __restrict__ bo, float* __restrict__ out) {
    char* sm = dynsm;
    uint32_t smb = smem_u32(sm);
    int t = threadIdx.x, lane = t & 31, warp = t >> 5;
    int b = blockIdx.y, i0 = blockIdx.x * 128;

    const uint4* qh4 = (const uint4*)(g_qh + (size_t)b * NPIX * C);
    const uint4* kh4 = (const uint4*)(g_kh + (size_t)b * NPIX * C);
    const uint4* vh4 = (const uint4*)(g_vh + (size_t)b * NPIX * C);

    for (int idx = t; idx < 1024; idx += 256) {
        int row = idx >> 3, c16 = idx & 7;
        uint32_t sw = SWZ((uint32_t)(row * 128 + c16 * 16));
        *(uint4*)(sm + SM_QH + sw) = qh4[(size_t)(i0 + row) * 8 + c16];
    }
    prefetch_kv(smb, 0, 0, kh4, vh4, t);
    CP_COMMIT;
    __syncthreads();

    int mm = lane >> 3, r8 = lane & 7;
    int qRowB  = (warp * 16 + (mm & 1) * 8 + r8) * 128;
    int qColB  = (mm >> 1) * 16;
    int kKeyOff = (mm >> 1) * 8 + r8;
    int kColB   = (mm & 1) * 16;
    int vKeyOff = (mm & 1) * 8 + r8;
    int vColB   = (mm >> 1) * 16;

    uint32_t qh[4][4];
    #pragma unroll
    for (int kc = 0; kc < 4; kc++)
        LDSM_X4(qh[kc], smb + SM_QH + SWZ((uint32_t)(qRowB + kc * 32 + qColB)));

    float O[8][4];
    #pragma unroll
    for (int ct = 0; ct < 8; ct++)
        #pragma unroll
        for (int e = 0; e < 4; e++) O[ct][e] = 0.f;
    float l0 = 0.f, l1 = 0.f;

    for (int jb = 0; jb < 32; jb++) {
        if (jb + 1 < 32) {
            prefetch_kv(smb, (jb + 1) & 1, (jb + 1) * 128, kh4, vh4, t);
            CP_COMMIT;
            CP_WAIT1;
        } else {
            CP_WAIT0;
        }
        __syncthreads();
        uint32_t kvb = smb + SM_KV + (jb & 1) * KVBUF;

        float Sv[16][4];
        #pragma unroll
        for (int nt = 0; nt < 16; nt++)
            #pragma unroll
            for (int e = 0; e < 4; e++) Sv[nt][e] = 0.f;

        #pragma unroll
        for (int kc = 0; kc < 4; kc++) {
            #pragma unroll
            for (int ntp = 0; ntp < 8; ntp++) {
                uint32_t rowb = (uint32_t)((ntp * 16 + kKeyOff) * 128 + kc * 32 + kColB);
                uint32_t bh[4];
                LDSM_X4(bh, kvb + KV_KH + SWZ(rowb));
                MMA(Sv[2 * ntp],     qh[kc], bh[0], bh[1]);
                MMA(Sv[2 * ntp + 1], qh[kc], bh[2], bh[3]);
            }
        }

        float rs0 = 0.f, rs1 = 0.f;
        #pragma unroll
        for (int nt = 0; nt < 16; nt++) {
            Sv[nt][0] = __expf(Sv[nt][0]);
            Sv[nt][1] = __expf(Sv[nt][1]);
            Sv[nt][2] = __expf(Sv[nt][2]);
            Sv[nt][3] = __expf(Sv[nt][3]);
            rs0 += Sv[nt][0] + Sv[nt][1];
            rs1 += Sv[nt][2] + Sv[nt][3];
        }
        rs0 += __shfl_xor_sync(0xffffffffu, rs0, 1);
        rs0 += __shfl_xor_sync(0xffffffffu, rs0, 2);
        rs1 += __shfl_xor_sync(0xffffffffu, rs1, 1);
        rs1 += __shfl_xor_sync(0xffffffffu, rs1, 2);
        l0 += rs0; l1 += rs1;

        #pragma unroll
        for (int kk = 0; kk < 8; kk++) {
            uint32_t ph[4];
            #pragma unroll
            for (int h = 0; h < 2; h++) {
                ph[2 * h]     = pack_bf16x2(Sv[2 * kk + h][0], Sv[2 * kk + h][1]);
                ph[2 * h + 1] = pack_bf16x2(Sv[2 * kk + h][2], Sv[2 * kk + h][3]);
            }
            #pragma unroll
            for (int ctp = 0; ctp < 4; ctp++) {
                uint32_t rowb = (uint32_t)((kk * 16 + vKeyOff) * 128 + ctp * 32 + vColB);
                uint32_t bh[4];
                LDSM_X4T(bh, kvb + KV_VH + SWZ(rowb));
                MMA(O[2 * ctp],     ph, bh[0], bh[1]);
                MMA(O[2 * ctp + 1], ph, bh[2], bh[3]);
            }
        }
        __syncthreads();
    }

    float* ws = (float*)(sm + 0);
    for (int idx = t; idx < C * C; idx += 256) {
        int oo = idx >> 6, cc = idx & 63;
        ws[cc * WPAD + oo] = Wo[idx];
    }
    float inv0 = 1.f / l0, inv1 = 1.f / l1;
    float* sO = (float*)(sm + 20480);
    int r = warp * 16 + (lane >> 2);
    #pragma unroll
    for (int ct = 0; ct < 8; ct++) {
        int ch = ct * 8 + (lane & 3) * 2;
        sO[ch * XPAD + r]           = O[ct][0] * inv0;
        sO[(ch + 1) * XPAD + r]     = O[ct][1] * inv0;
        sO[ch * XPAD + r + 8]       = O[ct][2] * inv1;
        sO[(ch + 1) * XPAD + r + 8] = O[ct][3] * inv1;
    }
    __syncthreads();

    int tx = t & 15, ty = t >> 4;
    int oo = ty * 4, ii = tx * 8;
    float acc[4][8];
    #pragma unroll
    for (int rr = 0; rr < 4; rr++)
        #pragma unroll
        for (int s = 0; s < 8; s++) acc[rr][s] = 0.f;

    #pragma unroll 4
    for (int c = 0; c < C; c++) {
        float xf[8], wf[4];
        *(float4*)(xf)     = *(const float4*)(sO + c * XPAD + ii);
        *(float4*)(xf + 4) = *(const float4*)(sO + c * XPAD + ii + 4);
        *(float4*)(wf)     = *(const float4*)(ws + c * WPAD + oo);
        #pragma unroll
        for (int rr = 0; rr < 4; rr++)
            #pragma unroll
            for (int s = 0; s < 8; s++) acc[rr][s] += wf[rr] * xf[s];
    }
    #pragma unroll
    for (int rr = 0; rr < 4; rr++) {
        int o = oo + rr;
        float bv = bo[o];
        size_t off = ((size_t)(b * C + o)) * NPIX + i0 + ii;
        float4 x0 = *(const float4*)(x + off);
        float4 x1 = *(const float4*)(x + off + 4);
        float tmp[8];
        tmp[0] = x0.x + acc[rr][0] + bv; tmp[1] = x0.y + acc[rr][1] + bv;
        tmp[2] = x0.z + acc[rr][2] + bv; tmp[3] = x0.w + acc[rr][3] + bv;
        tmp[4] = x1.x + acc[rr][4] + bv; tmp[5] = x1.y + acc[rr][5] + bv;
        tmp[6] = x1.z + acc[rr][6] + bv; tmp[7] = x1.w + acc[rr][7] + bv;
        *(float4*)(out + off)     = *(float4*)tmp;
        *(float4*)(out + off + 4) = *(float4*)(tmp + 4);
    }
}

// ============================================================================
extern "C" void kernel_launch(void* const* d_in, const int* in_sizes, int n_in,
                              void* d_out, int out_size) {
    const float* x     = (const float*)d_in[0];
    const float* Wq    = (const float*)d_in[1];
    const float* bq    = (const float*)d_in[2];
    const float* Wk    = (const float*)d_in[3];
    const float* bk    = (const float*)d_in[4];
    const float* Wv    = (const float*)d_in[5];
    const float* bv    = (const float*)d_in[6];
    const float* Wo    = (const float*)d_in[7];
    const float* bo    = (const float*)d_in[8];
    const float* gamma = (const float*)d_in[9];
    const float* beta  = (const float*)d_in[10];
    float* out = (float*)d_out;

    cudaFuncSetAttribute(qkv_kernel,  cudaFuncAttributeMaxDynamicSharedMemorySize, QKV_SMEM);
    cudaFuncSetAttribute(attn_kernel, cudaFuncAttributeMaxDynamicSharedMemorySize, SM_ATTN);

    gn_stats_kernel<<<dim3(NGROUPS, BATCH), 512>>>(x);
    qkv_kernel<<<dim3(NPIX / 128, BATCH), 384, QKV_SMEM>>>(x, Wq, bq, Wk, bk, Wv, bv, gamma, beta);
    attn_kernel<<<dim3(NPIX / 128, BATCH), 256, SM_ATTN>>>(x, Wo, bo, out);
}

// round 12
// speedup vs baseline: 2.9900x; 1.1139x over previous
#include <cuda_runtime.h>
#include <cuda_bf16.h>
#include <cuda_fp16.h>
#include <cstdint>
#include <cstddef>

#define BATCH   4
#define C       64
#define NPIX    4096
#define NGROUPS 32
#define WPAD    68
#define XPAD    132

// ---------------- scratch (device globals; no runtime allocation) ------------
__device__ __nv_bfloat16 g_qh[BATCH * NPIX * C];   // [b][n][c] rows of 128B
__device__ __nv_bfloat16 g_kh[BATCH * NPIX * C];
__device__ __half        g_vh[BATCH * NPIX * C];   // fp16 (PV MMA is f16)
__device__ float         g_stats[BATCH * NGROUPS * 2];

extern __shared__ char dynsm[];

// ---------------- helpers ----------------------------------------------------
__device__ __forceinline__ uint32_t smem_u32(const void* p) {
    uint32_t a;
    asm("{ .reg .u64 t; cvta.to.shared.u64 t, %1; cvt.u32.u64 %0, t; }" : "=r"(a) : "l"(p));
    return a;
}
#define SWZ(o) ((o) ^ (((o) >> 3) & 0x70))

#define CP_ASYNC(dst, src) \
    asm volatile("cp.async.cg.shared.global [%0], [%1], 16;" :: "r"(dst), "l"(src) : "memory")
#define CP_COMMIT asm volatile("cp.async.commit_group;" ::: "memory")
#define CP_WAIT1  asm volatile("cp.async.wait_group 1;" ::: "memory")
#define CP_WAIT0  asm volatile("cp.async.wait_group 0;" ::: "memory")

#define LDSM_X4(r, a) \
    asm volatile("ldmatrix.sync.aligned.m8n8.x4.shared.b16 {%0,%1,%2,%3}, [%4];" \
        : "=r"((r)[0]), "=r"((r)[1]), "=r"((r)[2]), "=r"((r)[3]) : "r"(a))
#define LDSM_X4T(r, a) \
    asm volatile("ldmatrix.sync.aligned.m8n8.x4.trans.shared.b16 {%0,%1,%2,%3}, [%4];" \
        : "=r"((r)[0]), "=r"((r)[1]), "=r"((r)[2]), "=r"((r)[3]) : "r"(a))

// D += A * B  (m16n8k16, bf16 in, f32 accum)
#define MMA(c, a, b0, b1) \
    asm volatile("mma.sync.aligned.m16n8k16.row.col.f32.bf16.bf16.f32 " \
        "{%0,%1,%2,%3}, {%4,%5,%6,%7}, {%8,%9}, {%0,%1,%2,%3};" \
        : "+f"((c)[0]), "+f"((c)[1]), "+f"((c)[2]), "+f"((c)[3]) \
        : "r"((a)[0]), "r"((a)[1]), "r"((a)[2]), "r"((a)[3]), "r"(b0), "r"(b1))

// D += A * B  (m16n8k16, fp16 in, f32 accum)
#define MMAH(c, a, b0, b1) \
    asm volatile("mma.sync.aligned.m16n8k16.row.col.f32.f16.f16.f32 " \
        "{%0,%1,%2,%3}, {%4,%5,%6,%7}, {%8,%9}, {%0,%1,%2,%3};" \
        : "+f"((c)[0]), "+f"((c)[1]), "+f"((c)[2]), "+f"((c)[3]) \
        : "r"((a)[0]), "r"((a)[1]), "r"((a)[2]), "r"((a)[3]), "r"(b0), "r"(b1))

#define ONES_F16X2 0x3C003C00u

__device__ __forceinline__ uint32_t pack_bf16x2(float lo, float hi) {
    uint32_t r;
    asm("cvt.rn.bf16x2.f32 %0, %1, %2;" : "=r"(r) : "f"(hi), "f"(lo));
    return r;
}
__device__ __forceinline__ uint32_t pack_f16x2(float lo, float hi) {
    __half2 h = __floats2half2_rn(lo, hi);
    return *(uint32_t*)&h;
}
__device__ __forceinline__ uint32_t exp2_f16x2(float lo, float hi) {
    __half2 h = h2exp2(__floats2half2_rn(lo, hi));
    return *(uint32_t*)&h;
}

// ============================================================================
// K0: GroupNorm statistics (512 threads) — unchanged
// ============================================================================
__global__ void __launch_bounds__(512) gn_stats_kernel(const float* __restrict__ x) {
    int g = blockIdx.x, b = blockIdx.y;
    const float* base = x + ((size_t)b * C + (size_t)g * 2) * NPIX;
    float s = 0.f, s2 = 0.f;
    const float4* p4 = (const float4*)base;
    for (int idx = threadIdx.x; idx < (2 * NPIX) / 4; idx += blockDim.x) {
        float4 v = p4[idx];
        s  += v.x + v.y + v.z + v.w;
        s2 += v.x * v.x + v.y * v.y + v.z * v.z + v.w * v.w;
    }
    __shared__ float rs[32], rs2[32];
    #pragma unroll
    for (int o = 16; o; o >>= 1) {
        s  += __shfl_xor_sync(0xffffffffu, s,  o);
        s2 += __shfl_xor_sync(0xffffffffu, s2, o);
    }
    int lane = threadIdx.x & 31, w = threadIdx.x >> 5;
    if (lane == 0) { rs[w] = s; rs2[w] = s2; }
    __syncthreads();
    if (w == 0) {
        s  = (lane < (int)(blockDim.x >> 5)) ? rs[lane]  : 0.f;
        s2 = (lane < (int)(blockDim.x >> 5)) ? rs2[lane] : 0.f;
        #pragma unroll
        for (int o = 16; o; o >>= 1) {
            s  += __shfl_xor_sync(0xffffffffu, s,  o);
            s2 += __shfl_xor_sync(0xffffffffu, s2, o);
        }
        if (lane == 0) {
            const float invn = 1.f / (2.f * NPIX);
            float mean = s * invn;
            float var  = s2 * invn - mean * mean;
            g_stats[(b * NGROUPS + g) * 2 + 0] = mean;
            g_stats[(b * NGROUPS + g) * 2 + 1] = rsqrtf(var + 1e-5f);
        }
    }
}

// ============================================================================
// K1: HMMA QKV (R11 structure). q scale now folds log2(e): 0.125*1.442695.
// V emitted as fp16 (pack_f16x2); q,k stay bf16.
// ============================================================================
#define QW_H     0
#define QW_L     24576
#define QX_H     49152
#define QX_L     65536
#define Q_SO     81920
#define QKV_SMEM 115712

__global__ void __launch_bounds__(384) qkv_kernel(
        const float* __restrict__ x,
        const float* __restrict__ Wq, const float* __restrict__ bq,
        const float* __restrict__ Wk, const float* __restrict__ bk,
        const float* __restrict__ Wv, const float* __restrict__ bv,
        const float* __restrict__ gamma, const float* __restrict__ beta) {
    char* sm = dynsm;
    uint32_t smb = smem_u32(sm);
    int t = threadIdx.x, lane = t & 31, warp = t >> 5;
    int b = blockIdx.y, i0 = blockIdx.x * 128;

    const float* Ws[3] = { Wq, Wk, Wv };
    for (int idx = t; idx < 3 * 1024; idx += 384) {
        int p = idx >> 10, rem = idx & 1023;
        int o = rem >> 4, c4 = (rem & 15) * 4;
        float4 w = *(const float4*)(Ws[p] + o * C + c4);
        uint32_t h01 = pack_bf16x2(w.x, w.y);
        uint32_t h23 = pack_bf16x2(w.z, w.w);
        uint32_t sw = SWZ((uint32_t)(o * 128 + c4 * 2));
        *(uint2*)(sm + QW_H + p * 8192 + sw) = make_uint2(h01, h23);
        uint32_t l01 = pack_bf16x2(w.x - __uint_as_float(h01 << 16),
                                   w.y - __uint_as_float(h01 & 0xffff0000u));
        uint32_t l23 = pack_bf16x2(w.z - __uint_as_float(h23 << 16),
                                   w.w - __uint_as_float(h23 & 0xffff0000u));
        *(uint2*)(sm + QW_L + p * 8192 + sw) = make_uint2(l01, l23);
    }
    const float* xb = x + (size_t)b * C * NPIX;
    for (int idx = t; idx < C * 32; idx += 384) {
        int c = idx >> 5, pix = (idx & 31) * 4;
        float4 v = *(const float4*)(xb + (size_t)c * NPIX + i0 + pix);
        int g = c >> 1;
        float mean = g_stats[(b * NGROUPS + g) * 2 + 0];
        float rstd = g_stats[(b * NGROUPS + g) * 2 + 1];
        float ga = gamma[c] * rstd, be = beta[c] - mean * ga;
        v.x = v.x * ga + be; v.y = v.y * ga + be;
        v.z = v.z * ga + be; v.w = v.w * ga + be;
        uint32_t h01 = pack_bf16x2(v.x, v.y);
        uint32_t h23 = pack_bf16x2(v.z, v.w);
        int half = (pix >= 64) ? 8192 : 0;
        uint32_t sw = SWZ((uint32_t)(c * 128 + (pix & 63) * 2));
        *(uint2*)(sm + QX_H + half + sw) = make_uint2(h01, h23);
        uint32_t l01 = pack_bf16x2(v.x - __uint_as_float(h01 << 16),
                                   v.y - __uint_as_float(h01 & 0xffff0000u));
        uint32_t l23 = pack_bf16x2(v.z - __uint_as_float(h23 << 16),
                                   v.w - __uint_as_float(h23 & 0xffff0000u));
        *(uint2*)(sm + QX_L + half + sw) = make_uint2(l01, l23);
    }
    __syncthreads();

    int proj = warp >> 2, warpM = warp & 3;
    int mm = lane >> 3, r8 = lane & 7;
    int aRowB = (warpM * 16 + (mm & 1) * 8 + r8) * 128;
    int aColB = (mm >> 1) * 16;
    int xKOff = (mm & 1) * 8 + r8;
    int xColB = (mm >> 1) * 16;

    uint32_t ah[4][4], al[4][4];
    #pragma unroll
    for (int kc = 0; kc < 4; kc++) {
        uint32_t sw = SWZ((uint32_t)(aRowB + kc * 32 + aColB));
        LDSM_X4(ah[kc], smb + QW_H + proj * 8192 + sw);
        LDSM_X4(al[kc], smb + QW_L + proj * 8192 + sw);
    }

    float acc[16][4];
    #pragma unroll
    for (int nt = 0; nt < 16; nt++)
        #pragma unroll
        for (int e = 0; e < 4; e++) acc[nt][e] = 0.f;

    #pragma unroll
    for (int npp = 0; npp < 8; npp++) {
        uint32_t xh_base = smb + QX_H + (npp >> 2) * 8192;
        uint32_t xl_base = smb + QX_L + (npp >> 2) * 8192;
        int np16 = npp & 3;
        #pragma unroll
        for (int kc = 0; kc < 4; kc++) {
            uint32_t rowb = (uint32_t)((kc * 16 + xKOff) * 128 + np16 * 32 + xColB);
            uint32_t bh[4], bl[4];
            LDSM_X4T(bh, xh_base + SWZ(rowb));
            MMA(acc[2 * npp],     ah[kc], bh[0], bh[1]);
            MMA(acc[2 * npp + 1], ah[kc], bh[2], bh[3]);
            MMA(acc[2 * npp],     al[kc], bh[0], bh[1]);
            MMA(acc[2 * npp + 1], al[kc], bh[2], bh[3]);
            LDSM_X4T(bl, xl_base + SWZ(rowb));
            MMA(acc[2 * npp],     ah[kc], bl[0], bl[1]);
            MMA(acc[2 * npp + 1], ah[kc], bl[2], bl[3]);
        }
    }

    const float* biasA = (proj == 0) ? bq : (proj == 1) ? bk : bv;
    // q folds softmax scale AND log2(e) for the exp2-based softmax
    float scale = (proj == 0) ? 0.125f * 1.44269504f : 1.0f;
    int o0 = warpM * 16 + (lane >> 2);
    int o1 = o0 + 8;
    float b0 = biasA[o0], b1 = biasA[o1];

    float* sO = (float*)(sm + Q_SO);
    int cw = t & 31, pg = t >> 5;

    #pragma unroll
    for (int rp = 0; rp < 3; rp++) {
        __syncthreads();
        if (proj == rp) {
            #pragma unroll
            for (int nt = 0; nt < 16; nt++) {
                int pix = nt * 8 + (lane & 3) * 2;
                *(float2*)(sO + o0 * XPAD + pix) =
                    make_float2((acc[nt][0] + b0) * scale, (acc[nt][1] + b0) * scale);
                *(float2*)(sO + o1 * XPAD + pix) =
                    make_float2((acc[nt][2] + b1) * scale, (acc[nt][3] + b1) * scale);
            }
        }
        __syncthreads();
        uint32_t* gh = (rp == 0) ? (uint32_t*)(g_qh + ((size_t)b * NPIX + i0) * C)
                     : (rp == 1) ? (uint32_t*)(g_kh + ((size_t)b * NPIX + i0) * C)
                                 : (uint32_t*)(g_vh + ((size_t)b * NPIX + i0) * C);
        for (int pix = pg; pix < 128; pix += 12) {
            float f0 = sO[(2 * cw) * XPAD + pix];
            float f1 = sO[(2 * cw + 1) * XPAD + pix];
            gh[pix * 32 + cw] = (rp == 2) ? pack_f16x2(f0, f1) : pack_bf16x2(f0, f1);
        }
    }
}

// ============================================================================
// K2: flash attention. S = qh*kh (bf16 MMA, pre-scaled by log2e);
// P = exp2(S) via h2exp2 -> fp16 fragments; PV + row-sum via f16 MMAs
// (row-sum = P x ones-matrix, B-frag constant, f32 accum, no shuffles).
// ============================================================================
#define SM_QH    0
#define SM_KV    16384
#define KVBUF    32768
#define KV_KH    0
#define KV_VH    16384
#define SM_ATTN  81920

__device__ __forceinline__ void prefetch_kv(uint32_t smb, int buf, int j0,
        const uint4* kh4, const uint4* vh4, int t) {
    uint32_t base = smb + SM_KV + buf * KVBUF;
    #pragma unroll
    for (int q = 0; q < 4; q++) {
        int idx = t + q * 256;
        int row = idx >> 3, c16 = idx & 7;
        uint32_t sw = SWZ((uint32_t)(row * 128 + c16 * 16));
        size_t off = (size_t)(j0 + row) * 8 + c16;
        CP_ASYNC(base + KV_KH + sw, kh4 + off);
        CP_ASYNC(base + KV_VH + sw, vh4 + off);
    }
}

__global__ void __launch_bounds__(256) attn_kernel(
        const float* __restrict__ x, const float* __restrict__ Wo,
        const float* __restrict__ bo, float* __restrict__ out) {
    char* sm = dynsm;
    uint32_t smb = smem_u32(sm);
    int t = threadIdx.x, lane = t & 31, warp = t >> 5;
    int b = blockIdx.y, i0 = blockIdx.x * 128;

    const uint4* qh4 = (const uint4*)(g_qh + (size_t)b * NPIX * C);
    const uint4* kh4 = (const uint4*)(g_kh + (size_t)b * NPIX * C);
    const uint4* vh4 = (const uint4*)(g_vh + (size_t)b * NPIX * C);

    for (int idx = t; idx < 1024; idx += 256) {
        int row = idx >> 3, c16 = idx & 7;
        uint32_t sw = SWZ((uint32_t)(row * 128 + c16 * 16));
        *(uint4*)(sm + SM_QH + sw) = qh4[(size_t)(i0 + row) * 8 + c16];
    }
    prefetch_kv(smb, 0, 0, kh4, vh4, t);
    CP_COMMIT;
    __syncthreads();

    int mm = lane >> 3, r8 = lane & 7;
    int qRowB  = (warp * 16 + (mm & 1) * 8 + r8) * 128;
    int qColB  = (mm >> 1) * 16;
    int kKeyOff = (mm >> 1) * 8 + r8;
    int kColB   = (mm & 1) * 16;
    int vKeyOff = (mm & 1) * 8 + r8;
    int vColB   = (mm >> 1) * 16;

    uint32_t qh[4][4];
    #pragma unroll
    for (int kc = 0; kc < 4; kc++)
        LDSM_X4(qh[kc], smb + SM_QH + SWZ((uint32_t)(qRowB + kc * 32 + qColB)));

    float O[8][4];
    #pragma unroll
    for (int ct = 0; ct < 8; ct++)
        #pragma unroll
        for (int e = 0; e < 4; e++) O[ct][e] = 0.f;
    float lsum[4] = { 0.f, 0.f, 0.f, 0.f };      // row-sum accumulator (ones-MMA)

    for (int jb = 0; jb < 32; jb++) {
        if (jb + 1 < 32) {
            prefetch_kv(smb, (jb + 1) & 1, (jb + 1) * 128, kh4, vh4, t);
            CP_COMMIT;
            CP_WAIT1;
        } else {
            CP_WAIT0;
        }
        __syncthreads();
        uint32_t kvb = smb + SM_KV + (jb & 1) * KVBUF;

        // ---- S = qh * kh (logits pre-scaled by log2e) ----
        float Sv[16][4];
        #pragma unroll
        for (int nt = 0; nt < 16; nt++)
            #pragma unroll
            for (int e = 0; e < 4; e++) Sv[nt][e] = 0.f;

        #pragma unroll
        for (int kc = 0; kc < 4; kc++) {
            #pragma unroll
            for (int ntp = 0; ntp < 8; ntp++) {
                uint32_t rowb = (uint32_t)((ntp * 16 + kKeyOff) * 128 + kc * 32 + kColB);
                uint32_t bh[4];
                LDSM_X4(bh, kvb + KV_KH + SWZ(rowb));
                MMA(Sv[2 * ntp],     qh[kc], bh[0], bh[1]);
                MMA(Sv[2 * ntp + 1], qh[kc], bh[2], bh[3]);
            }
        }

        // ---- P = exp2(S) in fp16; l += P*1 and O += P*V via f16 MMAs ----
        #pragma unroll
        for (int kk = 0; kk < 8; kk++) {
            uint32_t ph[4];
            #pragma unroll
            for (int h = 0; h < 2; h++) {
                ph[2 * h]     = exp2_f16x2(Sv[2 * kk + h][0], Sv[2 * kk + h][1]);
                ph[2 * h + 1] = exp2_f16x2(Sv[2 * kk + h][2], Sv[2 * kk + h][3]);
            }
            MMAH(lsum, ph, ONES_F16X2, ONES_F16X2);   // row sums, f32 accum
            #pragma unroll
            for (int ctp = 0; ctp < 4; ctp++) {
                uint32_t rowb = (uint32_t)((kk * 16 + vKeyOff) * 128 + ctp * 32 + vColB);
                uint32_t bh[4];
                LDSM_X4T(bh, kvb + KV_VH + SWZ(rowb));
                MMAH(O[2 * ctp],     ph, bh[0], bh[1]);
                MMAH(O[2 * ctp + 1], ph, bh[2], bh[3]);
            }
        }
        __syncthreads();
    }

    // ---- fused epilogue: Wo^T to smem, O/l transpose, proj + residual ----
    float* ws = (float*)(sm + 0);
    for (int idx = t; idx < C * C; idx += 256) {
        int oo = idx >> 6, cc = idx & 63;
        ws[cc * WPAD + oo] = Wo[idx];
    }
    // lsum[0] = row r sum (all cols equal), lsum[2] = row r+8 sum
    float inv0 = 1.f / lsum[0], inv1 = 1.f / lsum[2];
    float* sO = (float*)(sm + 20480);
    int r = warp * 16 + (lane >> 2);
    #pragma unroll
    for (int ct = 0; ct < 8; ct++) {
        int ch = ct * 8 + (lane & 3) * 2;
        sO[ch * XPAD + r]           = O[ct][0] * inv0;
        sO[(ch + 1) * XPAD + r]     = O[ct][1] * inv0;
        sO[ch * XPAD + r + 8]       = O[ct][2] * inv1;
        sO[(ch + 1) * XPAD + r + 8] = O[ct][3] * inv1;
    }
    __syncthreads();

    int tx = t & 15, ty = t >> 4;
    int oo = ty * 4, ii = tx * 8;
    float acc[4][8];
    #pragma unroll
    for (int rr = 0; rr < 4; rr++)
        #pragma unroll
        for (int s = 0; s < 8; s++) acc[rr][s] = 0.f;

    #pragma unroll 4
    for (int c = 0; c < C; c++) {
        float xf[8], wf[4];
        *(float4*)(xf)     = *(const float4*)(sO + c * XPAD + ii);
        *(float4*)(xf + 4) = *(const float4*)(sO + c * XPAD + ii + 4);
        *(float4*)(wf)     = *(const float4*)(ws + c * WPAD + oo);
        #pragma unroll
        for (int rr = 0; rr < 4; rr++)
            #pragma unroll
            for (int s = 0; s < 8; s++) acc[rr][s] += wf[rr] * xf[s];
    }
    #pragma unroll
    for (int rr = 0; rr < 4; rr++) {
        int o = oo + rr;
        float bv = bo[o];
        size_t off = ((size_t)(b * C + o)) * NPIX + i0 + ii;
        float4 x0 = *(const float4*)(x + off);
        float4 x1 = *(const float4*)(x + off + 4);
        float tmp[8];
        tmp[0] = x0.x + acc[rr][0] + bv; tmp[1] = x0.y + acc[rr][1] + bv;
        tmp[2] = x0.z + acc[rr][2] + bv; tmp[3] = x0.w + acc[rr][3] + bv;
        tmp[4] = x1.x + acc[rr][4] + bv; tmp[5] = x1.y + acc[rr][5] + bv;
        tmp[6] = x1.z + acc[rr][6] + bv; tmp[7] = x1.w + acc[rr][7] + bv;
        *(float4*)(out + off)     = *(float4*)tmp;
        *(float4*)(out + off + 4) = *(float4*)(tmp + 4);
    }
}

// ============================================================================
extern "C" void kernel_launch(void* const* d_in, const int* in_sizes, int n_in,
                              void* d_out, int out_size) {
    const float* x     = (const float*)d_in[0];
    const float* Wq    = (const float*)d_in[1];
    const float* bq    = (const float*)d_in[2];
    const float* Wk    = (const float*)d_in[3];
    const float* bk    = (const float*)d_in[4];
    const float* Wv    = (const float*)d_in[5];
    const float* bv    = (const float*)d_in[6];
    const float* Wo    = (const float*)d_in[7];
    const float* bo    = (const float*)d_in[8];
    const float* gamma = (const float*)d_in[9];
    const float* beta  = (const float*)d_in[10];
    float* out = (float*)d_out;

    cudaFuncSetAttribute(qkv_kernel,  cudaFuncAttributeMaxDynamicSharedMemorySize, QKV_SMEM);
    cudaFuncSetAttribute(attn_kernel, cudaFuncAttributeMaxDynamicSharedMemorySize, SM_ATTN);

    gn_stats_kernel<<<dim3(NGROUPS, BATCH), 512>>>(x);
    qkv_kernel<<<dim3(NPIX / 128, BATCH), 384, QKV_SMEM>>>(x, Wq, bq, Wk, bk, Wv, bv, gamma, beta);
    attn_kernel<<<dim3(NPIX / 128, BATCH), 256, SM_ATTN>>>(x, Wo, bo, out);
}

// round 15
// speedup vs baseline: 3.1629x; 1.0578x over previous
#include <cuda_runtime.h>
#include <cuda_bf16.h>
#include <cuda_fp16.h>
#include <cstdint>
#include <cstddef>

#define BATCH   4
#define C       64
#define NPIX    4096
#define NGROUPS 32
#define WPAD    68
#define XPAD    132

// ---------------- scratch (device globals; no runtime allocation) ------------
__device__ __nv_bfloat16 g_qh[BATCH * NPIX * C];   // [b][n][c] rows of 128B
__device__ __nv_bfloat16 g_kh[BATCH * NPIX * C];
__device__ __half        g_vh[BATCH * NPIX * C];   // fp16 (PV MMA is f16)
__device__ float2        g_part[BATCH * C];        // per-channel (sum, sumsq)

extern __shared__ char dynsm[];

// ---------------- helpers ----------------------------------------------------
__device__ __forceinline__ uint32_t smem_u32(const void* p) {
    uint32_t a;
    asm("{ .reg .u64 t; cvta.to.shared.u64 t, %1; cvt.u32.u64 %0, t; }" : "=r"(a) : "l"(p));
    return a;
}
#define SWZ(o) ((o) ^ (((o) >> 3) & 0x70))

#define CP_ASYNC(dst, src) \
    asm volatile("cp.async.cg.shared.global [%0], [%1], 16;" :: "r"(dst), "l"(src) : "memory")
#define CP_COMMIT asm volatile("cp.async.commit_group;" ::: "memory")
#define CP_WAIT1  asm volatile("cp.async.wait_group 1;" ::: "memory")
#define CP_WAIT0  asm volatile("cp.async.wait_group 0;" ::: "memory")

#define LDSM_X4(r, a) \
    asm volatile("ldmatrix.sync.aligned.m8n8.x4.shared.b16 {%0,%1,%2,%3}, [%4];" \
        : "=r"((r)[0]), "=r"((r)[1]), "=r"((r)[2]), "=r"((r)[3]) : "r"(a))
#define LDSM_X4T(r, a) \
    asm volatile("ldmatrix.sync.aligned.m8n8.x4.trans.shared.b16 {%0,%1,%2,%3}, [%4];" \
        : "=r"((r)[0]), "=r"((r)[1]), "=r"((r)[2]), "=r"((r)[3]) : "r"(a))

// D += A * B  (m16n8k16, bf16 in, f32 accum)
#define MMA(c, a, b0, b1) \
    asm volatile("mma.sync.aligned.m16n8k16.row.col.f32.bf16.bf16.f32 " \
        "{%0,%1,%2,%3}, {%4,%5,%6,%7}, {%8,%9}, {%0,%1,%2,%3};" \
        : "+f"((c)[0]), "+f"((c)[1]), "+f"((c)[2]), "+f"((c)[3]) \
        : "r"((a)[0]), "r"((a)[1]), "r"((a)[2]), "r"((a)[3]), "r"(b0), "r"(b1))

// D += A * B  (m16n8k16, fp16 in, f32 accum)
#define MMAH(c, a, b0, b1) \
    asm volatile("mma.sync.aligned.m16n8k16.row.col.f32.f16.f16.f32 " \
        "{%0,%1,%2,%3}, {%4,%5,%6,%7}, {%8,%9}, {%0,%1,%2,%3};" \
        : "+f"((c)[0]), "+f"((c)[1]), "+f"((c)[2]), "+f"((c)[3]) \
        : "r"((a)[0]), "r"((a)[1]), "r"((a)[2]), "r"((a)[3]), "r"(b0), "r"(b1))

#define ONES_F16X2 0x3C003C00u

__device__ __forceinline__ uint32_t pack_bf16x2(float lo, float hi) {
    uint32_t r;
    asm("cvt.rn.bf16x2.f32 %0, %1, %2;" : "=r"(r) : "f"(hi), "f"(lo));
    return r;
}
__device__ __forceinline__ uint32_t pack_f16x2(float lo, float hi) {
    __half2 h = __floats2half2_rn(lo, hi);
    return *(uint32_t*)&h;
}
__device__ __forceinline__ uint32_t exp2_f16x2(float lo, float hi) {
    __half2 h = h2exp2(__floats2half2_rn(lo, hi));
    return *(uint32_t*)&h;
}

// ============================================================================
// K0: GroupNorm partial sums, one CTA per CHANNEL (256 CTAs, better occupancy).
// qkv combines the two channel-partials of each group.
// ============================================================================
__global__ void __launch_bounds__(256) gn_stats_kernel(const float* __restrict__ x) {
    int c = blockIdx.x, b = blockIdx.y;
    const float* base = x + ((size_t)b * C + c) * NPIX;
    float s = 0.f, s2 = 0.f;
    const float4* p4 = (const float4*)base;
    #pragma unroll
    for (int q = 0; q < 4; q++) {
        float4 v = p4[threadIdx.x + q * 256];
        s  += v.x + v.y + v.z + v.w;
        s2 += v.x * v.x + v.y * v.y + v.z * v.z + v.w * v.w;
    }
    __shared__ float rs[8], rs2[8];
    #pragma unroll
    for (int o = 16; o; o >>= 1) {
        s  += __shfl_xor_sync(0xffffffffu, s,  o);
        s2 += __shfl_xor_sync(0xffffffffu, s2, o);
    }
    int lane = threadIdx.x & 31, w = threadIdx.x >> 5;
    if (lane == 0) { rs[w] = s; rs2[w] = s2; }
    __syncthreads();
    if (w == 0 && lane < 8) {
        s = rs[lane]; s2 = rs2[lane];
        #pragma unroll
        for (int o = 4; o; o >>= 1) {
            s  += __shfl_xor_sync(0xffu, s,  o);
            s2 += __shfl_xor_sync(0xffu, s2, o);
        }
        if (lane == 0) g_part[b * C + c] = make_float2(s, s2);
    }
}

// ============================================================================
// K1: HMMA QKV. Combines gn partials in a 32-thread preamble (smem ga/be).
// q scale folds 0.125*log2(e); V emitted fp16.
// ============================================================================
#define QW_H     0
#define QW_L     24576
#define QX_H     49152
#define QX_L     65536
#define Q_SO     81920
#define Q_GA     115712
#define Q_BE     115968
#define QKV_SMEM 116224

__global__ void __launch_bounds__(384) qkv_kernel(
        const float* __restrict__ x,
        const float* __restrict__ Wq, const float* __restrict__ bq,
        const float* __restrict__ Wk, const float* __restrict__ bk,
        const float* __restrict__ Wv, const float* __restrict__ bv,
        const float* __restrict__ gamma, const float* __restrict__ beta) {
    char* sm = dynsm;
    uint32_t smb = smem_u32(sm);
    int t = threadIdx.x, lane = t & 31, warp = t >> 5;
    int b = blockIdx.y, i0 = blockIdx.x * 128;

    // ---- combine gn partials -> per-channel ga/be in smem ----
    float* sga = (float*)(sm + Q_GA);
    float* sbe = (float*)(sm + Q_BE);
    if (t < NGROUPS) {
        float2 pa = g_part[b * C + 2 * t];
        float2 pb = g_part[b * C + 2 * t + 1];
        const float invn = 1.f / (2.f * NPIX);
        float mean = (pa.x + pb.x) * invn;
        float var  = (pa.y + pb.y) * invn - mean * mean;
        float rstd = rsqrtf(var + 1e-5f);
        #pragma unroll
        for (int j = 0; j < 2; j++) {
            int c = 2 * t + j;
            float ga = gamma[c] * rstd;
            sga[c] = ga;
            sbe[c] = beta[c] - mean * ga;
        }
    }
    __syncthreads();

    const float* Ws[3] = { Wq, Wk, Wv };
    for (int idx = t; idx < 3 * 1024; idx += 384) {
        int p = idx >> 10, rem = idx & 1023;
        int o = rem >> 4, c4 = (rem & 15) * 4;
        float4 w = *(const float4*)(Ws[p] + o * C + c4);
        uint32_t h01 = pack_bf16x2(w.x, w.y);
        uint32_t h23 = pack_bf16x2(w.z, w.w);
        uint32_t sw = SWZ((uint32_t)(o * 128 + c4 * 2));
        *(uint2*)(sm + QW_H + p * 8192 + sw) = make_uint2(h01, h23);
        uint32_t l01 = pack_bf16x2(w.x - __uint_as_float(h01 << 16),
                                   w.y - __uint_as_float(h01 & 0xffff0000u));
        uint32_t l23 = pack_bf16x2(w.z - __uint_as_float(h23 << 16),
                                   w.w - __uint_as_float(h23 & 0xffff0000u));
        *(uint2*)(sm + QW_L + p * 8192 + sw) = make_uint2(l01, l23);
    }
    const float* xb = x + (size_t)b * C * NPIX;
    for (int idx = t; idx < C * 32; idx += 384) {
        int c = idx >> 5, pix = (idx & 31) * 4;
        float4 v = *(const float4*)(xb + (size_t)c * NPIX + i0 + pix);
        float ga = sga[c], be = sbe[c];
        v.x = v.x * ga + be; v.y = v.y * ga + be;
        v.z = v.z * ga + be; v.w = v.w * ga + be;
        uint32_t h01 = pack_bf16x2(v.x, v.y);
        uint32_t h23 = pack_bf16x2(v.z, v.w);
        int half = (pix >= 64) ? 8192 : 0;
        uint32_t sw = SWZ((uint32_t)(c * 128 + (pix & 63) * 2));
        *(uint2*)(sm + QX_H + half + sw) = make_uint2(h01, h23);
        uint32_t l01 = pack_bf16x2(v.x - __uint_as_float(h01 << 16),
                                   v.y - __uint_as_float(h01 & 0xffff0000u));
        uint32_t l23 = pack_bf16x2(v.z - __uint_as_float(h23 << 16),
                                   v.w - __uint_as_float(h23 & 0xffff0000u));
        *(uint2*)(sm + QX_L + half + sw) = make_uint2(l01, l23);
    }
    __syncthreads();

    int proj = warp >> 2, warpM = warp & 3;
    int mm = lane >> 3, r8 = lane & 7;
    int aRowB = (warpM * 16 + (mm & 1) * 8 + r8) * 128;
    int aColB = (mm >> 1) * 16;
    int xKOff = (mm & 1) * 8 + r8;
    int xColB = (mm >> 1) * 16;

    uint32_t ah[4][4], al[4][4];
    #pragma unroll
    for (int kc = 0; kc < 4; kc++) {
        uint32_t sw = SWZ((uint32_t)(aRowB + kc * 32 + aColB));
        LDSM_X4(ah[kc], smb + QW_H + proj * 8192 + sw);
        LDSM_X4(al[kc], smb + QW_L + proj * 8192 + sw);
    }

    float acc[16][4];
    #pragma unroll
    for (int nt = 0; nt < 16; nt++)
        #pragma unroll
        for (int e = 0; e < 4; e++) acc[nt][e] = 0.f;

    #pragma unroll
    for (int npp = 0; npp < 8; npp++) {
        uint32_t xh_base = smb + QX_H + (npp >> 2) * 8192;
        uint32_t xl_base = smb + QX_L + (npp >> 2) * 8192;
        int np16 = npp & 3;
        #pragma unroll
        for (int kc = 0; kc < 4; kc++) {
            uint32_t rowb = (uint32_t)((kc * 16 + xKOff) * 128 + np16 * 32 + xColB);
            uint32_t bh[4], bl[4];
            LDSM_X4T(bh, xh_base + SWZ(rowb));
            MMA(acc[2 * npp],     ah[kc], bh[0], bh[1]);
            MMA(acc[2 * npp + 1], ah[kc], bh[2], bh[3]);
            MMA(acc[2 * npp],     al[kc], bh[0], bh[1]);
            MMA(acc[2 * npp + 1], al[kc], bh[2], bh[3]);
            LDSM_X4T(bl, xl_base + SWZ(rowb));
            MMA(acc[2 * npp],     ah[kc], bl[0], bl[1]);
            MMA(acc[2 * npp + 1], ah[kc], bl[2], bl[3]);
        }
    }

    const float* biasA = (proj == 0) ? bq : (proj == 1) ? bk : bv;
    float scale = (proj == 0) ? 0.125f * 1.44269504f : 1.0f;
    int o0 = warpM * 16 + (lane >> 2);
    int o1 = o0 + 8;
    float b0 = biasA[o0], b1 = biasA[o1];

    float* sO = (float*)(sm + Q_SO);
    int cw = t & 31, pg = t >> 5;

    #pragma unroll
    for (int rp = 0; rp < 3; rp++) {
        __syncthreads();
        if (proj == rp) {
            #pragma unroll
            for (int nt = 0; nt < 16; nt++) {
                int pix = nt * 8 + (lane & 3) * 2;
                *(float2*)(sO + o0 * XPAD + pix) =
                    make_float2((acc[nt][0] + b0) * scale, (acc[nt][1] + b0) * scale);
                *(float2*)(sO + o1 * XPAD + pix) =
                    make_float2((acc[nt][2] + b1) * scale, (acc[nt][3] + b1) * scale);
            }
        }
        __syncthreads();
        uint32_t* gh = (rp == 0) ? (uint32_t*)(g_qh + ((size_t)b * NPIX + i0) * C)
                     : (rp == 1) ? (uint32_t*)(g_kh + ((size_t)b * NPIX + i0) * C)
                                 : (uint32_t*)(g_vh + ((size_t)b * NPIX + i0) * C);
        for (int pix = pg; pix < 128; pix += 12) {
            float f0 = sO[(2 * cw) * XPAD + pix];
            float f1 = sO[(2 * cw + 1) * XPAD + pix];
            gh[pix * 32 + cw] = (rp == 2) ? pack_f16x2(f0, f1) : pack_bf16x2(f0, f1);
        }
    }
}

// ============================================================================
// K2: flash attention (S bf16 MMA pre-scaled by log2e; P=exp2 fp16; PV+rowsum
// f16 MMAs). NEW: output projection ALSO via f16 MMA (accum->A-frag identity
// on O, Wo staged fp16 in the K-operand pattern) — replaces 2048 FFMA/thread.
// ============================================================================
#define SM_QH    0
#define SM_KV    16384
#define KVBUF    32768
#define KV_KH    0
#define KV_VH    16384
#define SM_ATTN  81920

__device__ __forceinline__ void prefetch_kv(uint32_t smb, int buf, int j0,
        const uint4* kh4, const uint4* vh4, int t) {
    uint32_t base = smb + SM_KV + buf * KVBUF;
    #pragma unroll
    for (int q = 0; q < 4; q++) {
        int idx = t + q * 256;
        int row = idx >> 3, c16 = idx & 7;
        uint32_t sw = SWZ((uint32_t)(row * 128 + c16 * 16));
        size_t off = (size_t)(j0 + row) * 8 + c16;
        CP_ASYNC(base + KV_KH + sw, kh4 + off);
        CP_ASYNC(base + KV_VH + sw, vh4 + off);
    }
}

__global__ void __launch_bounds__(256) attn_kernel(
        const float* __restrict__ x, const float* __restrict__ Wo,
        const float* __restrict__ bo, float* __restrict__ out) {
    char* sm = dynsm;
    uint32_t smb = smem_u32(sm);
    int t = threadIdx.x, lane = t & 31, warp = t >> 5;
    int b = blockIdx.y, i0 = blockIdx.x * 128;

    const uint4* qh4 = (const uint4*)(g_qh + (size_t)b * NPIX * C);
    const uint4* kh4 = (const uint4*)(g_kh + (size_t)b * NPIX * C);
    const uint4* vh4 = (const uint4*)(g_vh + (size_t)b * NPIX * C);

    for (int idx = t; idx < 1024; idx += 256) {
        int row = idx >> 3, c16 = idx & 7;
        uint32_t sw = SWZ((uint32_t)(row * 128 + c16 * 16));
        *(uint4*)(sm + SM_QH + sw) = qh4[(size_t)(i0 + row) * 8 + c16];
    }
    prefetch_kv(smb, 0, 0, kh4, vh4, t);
    CP_COMMIT;
    __syncthreads();

    int mm = lane >> 3, r8 = lane & 7;
    int qRowB  = (warp * 16 + (mm & 1) * 8 + r8) * 128;
    int qColB  = (mm >> 1) * 16;
    int kKeyOff = (mm >> 1) * 8 + r8;      // also the Wo B-frag pattern
    int kColB   = (mm & 1) * 16;
    int vKeyOff = (mm & 1) * 8 + r8;
    int vColB   = (mm >> 1) * 16;

    uint32_t qh[4][4];
    #pragma unroll
    for (int kc = 0; kc < 4; kc++)
        LDSM_X4(qh[kc], smb + SM_QH + SWZ((uint32_t)(qRowB + kc * 32 + qColB)));

    float O[8][4];
    #pragma unroll
    for (int ct = 0; ct < 8; ct++)
        #pragma unroll
        for (int e = 0; e < 4; e++) O[ct][e] = 0.f;
    float lsum[4] = { 0.f, 0.f, 0.f, 0.f };

    for (int jb = 0; jb < 32; jb++) {
        if (jb + 1 < 32) {
            prefetch_kv(smb, (jb + 1) & 1, (jb + 1) * 128, kh4, vh4, t);
            CP_COMMIT;
            CP_WAIT1;
        } else {
            CP_WAIT0;
        }
        __syncthreads();
        uint32_t kvb = smb + SM_KV + (jb & 1) * KVBUF;

        float Sv[16][4];
        #pragma unroll
        for (int nt = 0; nt < 16; nt++)
            #pragma unroll
            for (int e = 0; e < 4; e++) Sv[nt][e] = 0.f;

        #pragma unroll
        for (int kc = 0; kc < 4; kc++) {
            #pragma unroll
            for (int ntp = 0; ntp < 8; ntp++) {
                uint32_t rowb = (uint32_t)((ntp * 16 + kKeyOff) * 128 + kc * 32 + kColB);
                uint32_t bh[4];
                LDSM_X4(bh, kvb + KV_KH + SWZ(rowb));
                MMA(Sv[2 * ntp],     qh[kc], bh[0], bh[1]);
                MMA(Sv[2 * ntp + 1], qh[kc], bh[2], bh[3]);
            }
        }

        #pragma unroll
        for (int kk = 0; kk < 8; kk++) {
            uint32_t ph[4];
            #pragma unroll
            for (int h = 0; h < 2; h++) {
                ph[2 * h]     = exp2_f16x2(Sv[2 * kk + h][0], Sv[2 * kk + h][1]);
                ph[2 * h + 1] = exp2_f16x2(Sv[2 * kk + h][2], Sv[2 * kk + h][3]);
            }
            MMAH(lsum, ph, ONES_F16X2, ONES_F16X2);
            #pragma unroll
            for (int ctp = 0; ctp < 4; ctp++) {
                uint32_t rowb = (uint32_t)((kk * 16 + vKeyOff) * 128 + ctp * 32 + vColB);
                uint32_t bh[4];
                LDSM_X4T(bh, kvb + KV_VH + SWZ(rowb));
                MMAH(O[2 * ctp],     ph, bh[0], bh[1]);
                MMAH(O[2 * ctp + 1], ph, bh[2], bh[3]);
            }
        }
        __syncthreads();
    }

    // ---- epilogue: stage Wo fp16 ([o][c] rows, K-operand pattern) ----
    for (int idx = t; idx < 1024; idx += 256) {
        int o = idx >> 4, c4 = (idx & 15) * 4;
        float4 w = *(const float4*)(Wo + o * C + c4);
        uint32_t sw = SWZ((uint32_t)(o * 128 + c4 * 2));
        *(uint2*)(sm + sw) = make_uint2(pack_f16x2(w.x, w.y), pack_f16x2(w.z, w.w));
    }
    __syncthreads();

    // ---- proj via f16 MMA: D[pix][o] = (O/l) * Wo^T ----
    float inv0 = 1.f / lsum[0], inv1 = 1.f / lsum[2];
    float Dp[8][4];
    #pragma unroll
    for (int nt = 0; nt < 8; nt++)
        #pragma unroll
        for (int e = 0; e < 4; e++) Dp[nt][e] = 0.f;

    #pragma unroll
    for (int kc = 0; kc < 4; kc++) {          // c-chunks of 16
        uint32_t po[4];
        po[0] = pack_f16x2(O[2 * kc][0] * inv0,     O[2 * kc][1] * inv0);
        po[1] = pack_f16x2(O[2 * kc][2] * inv1,     O[2 * kc][3] * inv1);
        po[2] = pack_f16x2(O[2 * kc + 1][0] * inv0, O[2 * kc + 1][1] * inv0);
        po[3] = pack_f16x2(O[2 * kc + 1][2] * inv1, O[2 * kc + 1][3] * inv1);
        #pragma unroll
        for (int n16 = 0; n16 < 4; n16++) {   // o-chunks of 16
            uint32_t rowb = (uint32_t)((n16 * 16 + kKeyOff) * 128 + kc * 32 + kColB);
            uint32_t bw[4];
            LDSM_X4(bw, smb + SWZ(rowb));
            MMAH(Dp[2 * n16],     po, bw[0], bw[1]);
            MMAH(Dp[2 * n16 + 1], po, bw[2], bw[3]);
        }
    }

    // ---- transpose Dp to smem [o][pix], then coalesced residual store ----
    float* sO = (float*)(sm + 20480);
    int r = warp * 16 + (lane >> 2);
    #pragma unroll
    for (int nt = 0; nt < 8; nt++) {
        int o = nt * 8 + (lane & 3) * 2;
        sO[o * XPAD + r]           = Dp[nt][0];
        sO[(o + 1) * XPAD + r]     = Dp[nt][1];
        sO[o * XPAD + r + 8]       = Dp[nt][2];
        sO[(o + 1) * XPAD + r + 8] = Dp[nt][3];
    }
    __syncthreads();

    int o = t >> 2, p0 = (t & 3) * 32;
    float bv = bo[o];
    size_t off = ((size_t)(b * C + o)) * NPIX + i0 + p0;
    #pragma unroll
    for (int e = 0; e < 32; e += 4) {
        float4 xx = *(const float4*)(x + off + e);
        float4 ss = *(const float4*)(sO + o * XPAD + p0 + e);
        float4 r4;
        r4.x = xx.x + ss.x + bv; r4.y = xx.y + ss.y + bv;
        r4.z = xx.z + ss.z + bv; r4.w = xx.w + ss.w + bv;
        *(float4*)(out + off + e) = r4;
    }
}

// ============================================================================
extern "C" void kernel_launch(void* const* d_in, const int* in_sizes, int n_in,
                              void* d_out, int out_size) {
    const float* x     = (const float*)d_in[0];
    const float* Wq    = (const float*)d_in[1];
    const float* bq    = (const float*)d_in[2];
    const float* Wk    = (const float*)d_in[3];
    const float* bk    = (const float*)d_in[4];
    const float* Wv    = (const float*)d_in[5];
    const float* bv    = (const float*)d_in[6];
    const float* Wo    = (const float*)d_in[7];
    const float* bo    = (const float*)d_in[8];
    const float* gamma = (const float*)d_in[9];
    const float* beta  = (const float*)d_in[10];
    float* out = (float*)d_out;

    cudaFuncSetAttribute(qkv_kernel,  cudaFuncAttributeMaxDynamicSharedMemorySize, QKV_SMEM);
    cudaFuncSetAttribute(attn_kernel, cudaFuncAttributeMaxDynamicSharedMemorySize, SM_ATTN);

    gn_stats_kernel<<<dim3(C, BATCH), 256>>>(x);
    qkv_kernel<<<dim3(NPIX / 128, BATCH), 384, QKV_SMEM>>>(x, Wq, bq, Wk, bk, Wv, bv, gamma, beta);
    attn_kernel<<<dim3(NPIX / 128, BATCH), 256, SM_ATTN>>>(x, Wo, bo, out);
}

// round 17
// speedup vs baseline: 3.3497x; 1.0591x over previous
#include <cuda_runtime.h>
#include <cuda_bf16.h>
#include <cuda_fp16.h>
#include <cstdint>
#include <cstddef>

#define BATCH   4
#define C       64
#define NPIX    4096
#define NGROUPS 32
#define WPAD    68
#define XPAD    132
#define OPAD    66

// ---------------- scratch (device globals; no runtime allocation) ------------
__device__ __nv_bfloat16 g_qh[BATCH * NPIX * C];   // [b][n][c] rows of 128B
__device__ __nv_bfloat16 g_kh[BATCH * NPIX * C];
__device__ __half        g_vh[BATCH * NPIX * C];   // fp16 (PV MMA is f16)
__device__ float2        g_part[BATCH * C * 2];    // per half-channel (sum, sumsq)

extern __shared__ char dynsm[];

// ---------------- helpers ----------------------------------------------------
__device__ __forceinline__ uint32_t smem_u32(const void* p) {
    uint32_t a;
    asm("{ .reg .u64 t; cvta.to.shared.u64 t, %1; cvt.u32.u64 %0, t; }" : "=r"(a) : "l"(p));
    return a;
}
#define SWZ(o) ((o) ^ (((o) >> 3) & 0x70))

#define CP_ASYNC(dst, src) \
    asm volatile("cp.async.cg.shared.global [%0], [%1], 16;" :: "r"(dst), "l"(src) : "memory")
#define CP_COMMIT asm volatile("cp.async.commit_group;" ::: "memory")
#define CP_WAIT1  asm volatile("cp.async.wait_group 1;" ::: "memory")
#define CP_WAIT0  asm volatile("cp.async.wait_group 0;" ::: "memory")

#define LDSM_X4(r, a) \
    asm volatile("ldmatrix.sync.aligned.m8n8.x4.shared.b16 {%0,%1,%2,%3}, [%4];" \
        : "=r"((r)[0]), "=r"((r)[1]), "=r"((r)[2]), "=r"((r)[3]) : "r"(a))
#define LDSM_X4T(r, a) \
    asm volatile("ldmatrix.sync.aligned.m8n8.x4.trans.shared.b16 {%0,%1,%2,%3}, [%4];" \
        : "=r"((r)[0]), "=r"((r)[1]), "=r"((r)[2]), "=r"((r)[3]) : "r"(a))

// D += A * B  (m16n8k16, bf16 in, f32 accum)
#define MMA(c, a, b0, b1) \
    asm volatile("mma.sync.aligned.m16n8k16.row.col.f32.bf16.bf16.f32 " \
        "{%0,%1,%2,%3}, {%4,%5,%6,%7}, {%8,%9}, {%0,%1,%2,%3};" \
        : "+f"((c)[0]), "+f"((c)[1]), "+f"((c)[2]), "+f"((c)[3]) \
        : "r"((a)[0]), "r"((a)[1]), "r"((a)[2]), "r"((a)[3]), "r"(b0), "r"(b1))

// D += A * B  (m16n8k16, fp16 in, f32 accum)
#define MMAH(c, a, b0, b1) \
    asm volatile("mma.sync.aligned.m16n8k16.row.col.f32.f16.f16.f32 " \
        "{%0,%1,%2,%3}, {%4,%5,%6,%7}, {%8,%9}, {%0,%1,%2,%3};" \
        : "+f"((c)[0]), "+f"((c)[1]), "+f"((c)[2]), "+f"((c)[3]) \
        : "r"((a)[0]), "r"((a)[1]), "r"((a)[2]), "r"((a)[3]), "r"(b0), "r"(b1))

#define ONES_F16X2 0x3C003C00u

__device__ __forceinline__ uint32_t pack_bf16x2(float lo, float hi) {
    uint32_t r;
    asm("cvt.rn.bf16x2.f32 %0, %1, %2;" : "=r"(r) : "f"(hi), "f"(lo));
    return r;
}
__device__ __forceinline__ uint32_t pack_f16x2(float lo, float hi) {
    __half2 h = __floats2half2_rn(lo, hi);
    return *(uint32_t*)&h;
}
__device__ __forceinline__ uint32_t exp2_f16x2(float lo, float hi) {
    __half2 h = h2exp2(__floats2half2_rn(lo, hi));
    return *(uint32_t*)&h;
}

// ============================================================================
// K0: GroupNorm partial sums, one CTA per HALF-channel (512 CTAs).
// ============================================================================
__global__ void __launch_bounds__(256) gn_stats_kernel(const float* __restrict__ x) {
    int ch = blockIdx.x;                 // 0..127: c*2 + half
    int c = ch >> 1, half = ch & 1, b = blockIdx.y;
    const float4* p4 = (const float4*)(x + ((size_t)b * C + c) * NPIX + half * (NPIX / 2));
    float s = 0.f, s2 = 0.f;
    #pragma unroll
    for (int q = 0; q < 2; q++) {
        float4 v = p4[threadIdx.x + q * 256];
        s  += v.x + v.y + v.z + v.w;
        s2 += v.x * v.x + v.y * v.y + v.z * v.z + v.w * v.w;
    }
    __shared__ float rs[8], rs2[8];
    #pragma unroll
    for (int o = 16; o; o >>= 1) {
        s  += __shfl_xor_sync(0xffffffffu, s,  o);
        s2 += __shfl_xor_sync(0xffffffffu, s2, o);
    }
    int lane = threadIdx.x & 31, w = threadIdx.x >> 5;
    if (lane == 0) { rs[w] = s; rs2[w] = s2; }
    __syncthreads();
    if (w == 0 && lane < 8) {
        s = rs[lane]; s2 = rs2[lane];
        #pragma unroll
        for (int o = 4; o; o >>= 1) {
            s  += __shfl_xor_sync(0xffu, s,  o);
            s2 += __shfl_xor_sync(0xffu, s2, o);
        }
        if (lane == 0) g_part[(b * C + c) * 2 + half] = make_float2(s, s2);
    }
}

// ============================================================================
// K1: HMMA QKV. Combines 4 gn partials per group in a 32-thread preamble.
// sO epilogue staging is now [pix][OPAD] -> conflict-free reader LDS +
// coalesced global stores. q scale folds 0.125*log2(e); V emitted fp16.
// ============================================================================
#define QW_H     0
#define QW_L     24576
#define QX_H     49152
#define QX_L     65536
#define Q_SO     81920
#define Q_GA     115712
#define Q_BE     115968
#define QKV_SMEM 116224

__global__ void __launch_bounds__(384) qkv_kernel(
        const float* __restrict__ x,
        const float* __restrict__ Wq, const float* __restrict__ bq,
        const float* __restrict__ Wk, const float* __restrict__ bk,
        const float* __restrict__ Wv, const float* __restrict__ bv,
        const float* __restrict__ gamma, const float* __restrict__ beta) {
    char* sm = dynsm;
    uint32_t smb = smem_u32(sm);
    int t = threadIdx.x, lane = t & 31, warp = t >> 5;
    int b = blockIdx.y, i0 = blockIdx.x * 128;

    // ---- combine gn partials -> per-channel ga/be in smem ----
    float* sga = (float*)(sm + Q_GA);
    float* sbe = (float*)(sm + Q_BE);
    if (t < NGROUPS) {
        float2 p0_ = g_part[(b * C + 2 * t) * 2 + 0];
        float2 p1_ = g_part[(b * C + 2 * t) * 2 + 1];
        float2 p2_ = g_part[(b * C + 2 * t + 1) * 2 + 0];
        float2 p3_ = g_part[(b * C + 2 * t + 1) * 2 + 1];
        const float invn = 1.f / (2.f * NPIX);
        float mean = (p0_.x + p1_.x + p2_.x + p3_.x) * invn;
        float var  = (p0_.y + p1_.y + p2_.y + p3_.y) * invn - mean * mean;
        float rstd = rsqrtf(var + 1e-5f);
        #pragma unroll
        for (int j = 0; j < 2; j++) {
            int c = 2 * t + j;
            float ga = gamma[c] * rstd;
            sga[c] = ga;
            sbe[c] = beta[c] - mean * ga;
        }
    }
    __syncthreads();

    const float* Ws[3] = { Wq, Wk, Wv };
    for (int idx = t; idx < 3 * 1024; idx += 384) {
        int p = idx >> 10, rem = idx & 1023;
        int o = rem >> 4, c4 = (rem & 15) * 4;
        float4 w = *(const float4*)(Ws[p] + o * C + c4);
        uint32_t h01 = pack_bf16x2(w.x, w.y);
        uint32_t h23 = pack_bf16x2(w.z, w.w);
        uint32_t sw = SWZ((uint32_t)(o * 128 + c4 * 2));
        *(uint2*)(sm + QW_H + p * 8192 + sw) = make_uint2(h01, h23);
        uint32_t l01 = pack_bf16x2(w.x - __uint_as_float(h01 << 16),
                                   w.y - __uint_as_float(h01 & 0xffff0000u));
        uint32_t l23 = pack_bf16x2(w.z - __uint_as_float(h23 << 16),
                                   w.w - __uint_as_float(h23 & 0xffff0000u));
        *(uint2*)(sm + QW_L + p * 8192 + sw) = make_uint2(l01, l23);
    }
    const float* xb = x + (size_t)b * C * NPIX;
    for (int idx = t; idx < C * 32; idx += 384) {
        int c = idx >> 5, pix = (idx & 31) * 4;
        float4 v = *(const float4*)(xb + (size_t)c * NPIX + i0 + pix);
        float ga = sga[c], be = sbe[c];
        v.x = v.x * ga + be; v.y = v.y * ga + be;
        v.z = v.z * ga + be; v.w = v.w * ga + be;
        uint32_t h01 = pack_bf16x2(v.x, v.y);
        uint32_t h23 = pack_bf16x2(v.z, v.w);
        int half = (pix >= 64) ? 8192 : 0;
        uint32_t sw = SWZ((uint32_t)(c * 128 + (pix & 63) * 2));
        *(uint2*)(sm + QX_H + half + sw) = make_uint2(h01, h23);
        uint32_t l01 = pack_bf16x2(v.x - __uint_as_float(h01 << 16),
                                   v.y - __uint_as_float(h01 & 0xffff0000u));
        uint32_t l23 = pack_bf16x2(v.z - __uint_as_float(h23 << 16),
                                   v.w - __uint_as_float(h23 & 0xffff0000u));
        *(uint2*)(sm + QX_L + half + sw) = make_uint2(l01, l23);
    }
    __syncthreads();

    int proj = warp >> 2, warpM = warp & 3;
    int mm = lane >> 3, r8 = lane & 7;
    int aRowB = (warpM * 16 + (mm & 1) * 8 + r8) * 128;
    int aColB = (mm >> 1) * 16;
    int xKOff = (mm & 1) * 8 + r8;
    int xColB = (mm >> 1) * 16;

    uint32_t ah[4][4], al[4][4];
    #pragma unroll
    for (int kc = 0; kc < 4; kc++) {
        uint32_t sw = SWZ((uint32_t)(aRowB + kc * 32 + aColB));
        LDSM_X4(ah[kc], smb + QW_H + proj * 8192 + sw);
        LDSM_X4(al[kc], smb + QW_L + proj * 8192 + sw);
    }

    float acc[16][4];
    #pragma unroll
    for (int nt = 0; nt < 16; nt++)
        #pragma unroll
        for (int e = 0; e < 4; e++) acc[nt][e] = 0.f;

    #pragma unroll
    for (int npp = 0; npp < 8; npp++) {
        uint32_t xh_base = smb + QX_H + (npp >> 2) * 8192;
        uint32_t xl_base = smb + QX_L + (npp >> 2) * 8192;
        int np16 = npp & 3;
        #pragma unroll
        for (int kc = 0; kc < 4; kc++) {
            uint32_t rowb = (uint32_t)((kc * 16 + xKOff) * 128 + np16 * 32 + xColB);
            uint32_t bh[4], bl[4];
            LDSM_X4T(bh, xh_base + SWZ(rowb));
            MMA(acc[2 * npp],     ah[kc], bh[0], bh[1]);
            MMA(acc[2 * npp + 1], ah[kc], bh[2], bh[3]);
            MMA(acc[2 * npp],     al[kc], bh[0], bh[1]);
            MMA(acc[2 * npp + 1], al[kc], bh[2], bh[3]);
            LDSM_X4T(bl, xl_base + SWZ(rowb));
            MMA(acc[2 * npp],     ah[kc], bl[0], bl[1]);
            MMA(acc[2 * npp + 1], ah[kc], bl[2], bl[3]);
        }
    }

    const float* biasA = (proj == 0) ? bq : (proj == 1) ? bk : bv;
    float scale = (proj == 0) ? 0.125f * 1.44269504f : 1.0f;
    int o0 = warpM * 16 + (lane >> 2);
    int o1 = o0 + 8;
    float b0 = biasA[o0], b1 = biasA[o1];

    float* sO = (float*)(sm + Q_SO);     // [128][OPAD] floats = 33792 B
    int cw = t & 31, pg = t >> 5;

    #pragma unroll
    for (int rp = 0; rp < 3; rp++) {
        __syncthreads();
        if (proj == rp) {
            #pragma unroll
            for (int nt = 0; nt < 16; nt++) {
                int pix = nt * 8 + (lane & 3) * 2;
                sO[pix * OPAD + o0]       = (acc[nt][0] + b0) * scale;
                sO[(pix + 1) * OPAD + o0] = (acc[nt][1] + b0) * scale;
                sO[pix * OPAD + o1]       = (acc[nt][2] + b1) * scale;
                sO[(pix + 1) * OPAD + o1] = (acc[nt][3] + b1) * scale;
            }
        }
        __syncthreads();
        uint32_t* gh = (rp == 0) ? (uint32_t*)(g_qh + ((size_t)b * NPIX + i0) * C)
                     : (rp == 1) ? (uint32_t*)(g_kh + ((size_t)b * NPIX + i0) * C)
                                 : (uint32_t*)(g_vh + ((size_t)b * NPIX + i0) * C);
        for (int pix = pg; pix < 128; pix += 12) {
            float2 f = *(const float2*)(sO + pix * OPAD + 2 * cw);
            gh[pix * 32 + cw] = (rp == 2) ? pack_f16x2(f.x, f.y) : pack_bf16x2(f.x, f.y);
        }
    }
}

// ============================================================================
// K2: flash attention + MMA output projection (unchanged from R15)
// ============================================================================
#define SM_QH    0
#define SM_KV    16384
#define KVBUF    32768
#define KV_KH    0
#define KV_VH    16384
#define SM_ATTN  81920

__device__ __forceinline__ void prefetch_kv(uint32_t smb, int buf, int j0,
        const uint4* kh4, const uint4* vh4, int t) {
    uint32_t base = smb + SM_KV + buf * KVBUF;
    #pragma unroll
    for (int q = 0; q < 4; q++) {
        int idx = t + q * 256;
        int row = idx >> 3, c16 = idx & 7;
        uint32_t sw = SWZ((uint32_t)(row * 128 + c16 * 16));
        size_t off = (size_t)(j0 + row) * 8 + c16;
        CP_ASYNC(base + KV_KH + sw, kh4 + off);
        CP_ASYNC(base + KV_VH + sw, vh4 + off);
    }
}

__global__ void __launch_bounds__(256) attn_kernel(
        const float* __restrict__ x, const float* __restrict__ Wo,
        const float* __restrict__ bo, float* __restrict__ out) {
    char* sm = dynsm;
    uint32_t smb = smem_u32(sm);
    int t = threadIdx.x, lane = t & 31, warp = t >> 5;
    int b = blockIdx.y, i0 = blockIdx.x * 128;

    const uint4* qh4 = (const uint4*)(g_qh + (size_t)b * NPIX * C);
    const uint4* kh4 = (const uint4*)(g_kh + (size_t)b * NPIX * C);
    const uint4* vh4 = (const uint4*)(g_vh + (size_t)b * NPIX * C);

    for (int idx = t; idx < 1024; idx += 256) {
        int row = idx >> 3, c16 = idx & 7;
        uint32_t sw = SWZ((uint32_t)(row * 128 + c16 * 16));
        *(uint4*)(sm + SM_QH + sw) = qh4[(size_t)(i0 + row) * 8 + c16];
    }
    prefetch_kv(smb, 0, 0, kh4, vh4, t);
    CP_COMMIT;
    __syncthreads();

    int mm = lane >> 3, r8 = lane & 7;
    int qRowB  = (warp * 16 + (mm & 1) * 8 + r8) * 128;
    int qColB  = (mm >> 1) * 16;
    int kKeyOff = (mm >> 1) * 8 + r8;
    int kColB   = (mm & 1) * 16;
    int vKeyOff = (mm & 1) * 8 + r8;
    int vColB   = (mm >> 1) * 16;

    uint32_t qh[4][4];
    #pragma unroll
    for (int kc = 0; kc < 4; kc++)
        LDSM_X4(qh[kc], smb + SM_QH + SWZ((uint32_t)(qRowB + kc * 32 + qColB)));

    float O[8][4];
    #pragma unroll
    for (int ct = 0; ct < 8; ct++)
        #pragma unroll
        for (int e = 0; e < 4; e++) O[ct][e] = 0.f;
    float lsum[4] = { 0.f, 0.f, 0.f, 0.f };

    for (int jb = 0; jb < 32; jb++) {
        if (jb + 1 < 32) {
            prefetch_kv(smb, (jb + 1) & 1, (jb + 1) * 128, kh4, vh4, t);
            CP_COMMIT;
            CP_WAIT1;
        } else {
            CP_WAIT0;
        }
        __syncthreads();
        uint32_t kvb = smb + SM_KV + (jb & 1) * KVBUF;

        float Sv[16][4];
        #pragma unroll
        for (int nt = 0; nt < 16; nt++)
            #pragma unroll
            for (int e = 0; e < 4; e++) Sv[nt][e] = 0.f;

        #pragma unroll
        for (int kc = 0; kc < 4; kc++) {
            #pragma unroll
            for (int ntp = 0; ntp < 8; ntp++) {
                uint32_t rowb = (uint32_t)((ntp * 16 + kKeyOff) * 128 + kc * 32 + kColB);
                uint32_t bh[4];
                LDSM_X4(bh, kvb + KV_KH + SWZ(rowb));
                MMA(Sv[2 * ntp],     qh[kc], bh[0], bh[1]);
                MMA(Sv[2 * ntp + 1], qh[kc], bh[2], bh[3]);
            }
        }

        #pragma unroll
        for (int kk = 0; kk < 8; kk++) {
            uint32_t ph[4];
            #pragma unroll
            for (int h = 0; h < 2; h++) {
                ph[2 * h]     = exp2_f16x2(Sv[2 * kk + h][0], Sv[2 * kk + h][1]);
                ph[2 * h + 1] = exp2_f16x2(Sv[2 * kk + h][2], Sv[2 * kk + h][3]);
            }
            MMAH(lsum, ph, ONES_F16X2, ONES_F16X2);
            #pragma unroll
            for (int ctp = 0; ctp < 4; ctp++) {
                uint32_t rowb = (uint32_t)((kk * 16 + vKeyOff) * 128 + ctp * 32 + vColB);
                uint32_t bh[4];
                LDSM_X4T(bh, kvb + KV_VH + SWZ(rowb));
                MMAH(O[2 * ctp],     ph, bh[0], bh[1]);
                MMAH(O[2 * ctp + 1], ph, bh[2], bh[3]);
            }
        }
        __syncthreads();
    }

    // ---- epilogue: stage Wo fp16 ([o][c] rows, K-operand pattern) ----
    for (int idx = t; idx < 1024; idx += 256) {
        int o = idx >> 4, c4 = (idx & 15) * 4;
        float4 w = *(const float4*)(Wo + o * C + c4);
        uint32_t sw = SWZ((uint32_t)(o * 128 + c4 * 2));
        *(uint2*)(sm + sw) = make_uint2(pack_f16x2(w.x, w.y), pack_f16x2(w.z, w.w));
    }
    __syncthreads();

    // ---- proj via f16 MMA: D[pix][o] = (O/l) * Wo^T ----
    float inv0 = 1.f / lsum[0], inv1 = 1.f / lsum[2];
    float Dp[8][4];
    #pragma unroll
    for (int nt = 0; nt < 8; nt++)
        #pragma unroll
        for (int e = 0; e < 4; e++) Dp[nt][e] = 0.f;

    #pragma unroll
    for (int kc = 0; kc < 4; kc++) {
        uint32_t po[4];
        po[0] = pack_f16x2(O[2 * kc][0] * inv0,     O[2 * kc][1] * inv0);
        po[1] = pack_f16x2(O[2 * kc][2] * inv1,     O[2 * kc][3] * inv1);
        po[2] = pack_f16x2(O[2 * kc + 1][0] * inv0, O[2 * kc + 1][1] * inv0);
        po[3] = pack_f16x2(O[2 * kc + 1][2] * inv1, O[2 * kc + 1][3] * inv1);
        #pragma unroll
        for (int n16 = 0; n16 < 4; n16++) {
            uint32_t rowb = (uint32_t)((n16 * 16 + kKeyOff) * 128 + kc * 32 + kColB);
            uint32_t bw[4];
            LDSM_X4(bw, smb + SWZ(rowb));
            MMAH(Dp[2 * n16],     po, bw[0], bw[1]);
            MMAH(Dp[2 * n16 + 1], po, bw[2], bw[3]);
        }
    }

    // ---- transpose Dp to smem [o][pix], then coalesced residual store ----
    float* sO = (float*)(sm + 20480);
    int r = warp * 16 + (lane >> 2);
    #pragma unroll
    for (int nt = 0; nt < 8; nt++) {
        int o = nt * 8 + (lane & 3) * 2;
        sO[o * XPAD + r]           = Dp[nt][0];
        sO[(o + 1) * XPAD + r]     = Dp[nt][1];
        sO[o * XPAD + r + 8]       = Dp[nt][2];
        sO[(o + 1) * XPAD + r + 8] = Dp[nt][3];
    }
    __syncthreads();

    int o = t >> 2, p0 = (t & 3) * 32;
    float bv = bo[o];
    size_t off = ((size_t)(b * C + o)) * NPIX + i0 + p0;
    #pragma unroll
    for (int e = 0; e < 32; e += 4) {
        float4 xx = *(const float4*)(x + off + e);
        float4 ss = *(const float4*)(sO + o * XPAD + p0 + e);
        float4 r4;
        r4.x = xx.x + ss.x + bv; r4.y = xx.y + ss.y + bv;
        r4.z = xx.z + ss.z + bv; r4.w = xx.w + ss.w + bv;
        *(float4*)(out + off + e) = r4;
    }
}

// ============================================================================
extern "C" void kernel_launch(void* const* d_in, const int* in_sizes, int n_in,
                              void* d_out, int out_size) {
    const float* x     = (const float*)d_in[0];
    const float* Wq    = (const float*)d_in[1];
    const float* bq    = (const float*)d_in[2];
    const float* Wk    = (const float*)d_in[3];
    const float* bk    = (const float*)d_in[4];
    const float* Wv    = (const float*)d_in[5];
    const float* bv    = (const float*)d_in[6];
    const float* Wo    = (const float*)d_in[7];
    const float* bo    = (const float*)d_in[8];
    const float* gamma = (const float*)d_in[9];
    const float* beta  = (const float*)d_in[10];
    float* out = (float*)d_out;

    cudaFuncSetAttribute(qkv_kernel,  cudaFuncAttributeMaxDynamicSharedMemorySize, QKV_SMEM);
    cudaFuncSetAttribute(attn_kernel, cudaFuncAttributeMaxDynamicSharedMemorySize, SM_ATTN);

    gn_stats_kernel<<<dim3(2 * C, BATCH), 256>>>(x);
    qkv_kernel<<<dim3(NPIX / 128, BATCH), 384, QKV_SMEM>>>(x, Wq, bq, Wk, bk, Wv, bv, gamma, beta);
    attn_kernel<<<dim3(NPIX / 128, BATCH), 256, SM_ATTN>>>(x, Wo, bo, out);
}